// round 11
// baseline (speedup 1.0000x reference)
#include <cuda_runtime.h>
#include <cuda_bf16.h>
#include <cstdint>

// ---------------- problem constants ----------------
#define BATCH 4
#define SEQ 4096
#define DMODEL 1024
#define WIN 256
#define NWIN 31              // window starts 0,128,...,3840
#define NBW (BATCH * NWIN)   // 124
#define MTOK (BATCH * SEQ)   // 16384

typedef __nv_bfloat16 bf16;

// ---------------- scratch (static device globals, no allocs) ----------------
__device__ float g_v[(size_t)MTOK * DMODEL];
__device__ float g_s[(size_t)NBW * WIN * WIN];
__device__ float g_ow[(size_t)NBW * WIN * DMODEL];

__device__ bf16 g_xh[(size_t)MTOK * DMODEL];
__device__ bf16 g_xl[(size_t)MTOK * DMODEL];
__device__ bf16 g_qh[(size_t)MTOK * DMODEL];
__device__ bf16 g_ql[(size_t)MTOK * DMODEL];
__device__ bf16 g_kh[(size_t)MTOK * DMODEL];
__device__ bf16 g_kl[(size_t)MTOK * DMODEL];
__device__ bf16 g_vth[(size_t)MTOK * DMODEL];   // per-batch V^T [1024][4096]
__device__ bf16 g_vtl[(size_t)MTOK * DMODEL];
__device__ bf16 g_sh[(size_t)NBW * WIN * WIN];
__device__ bf16 g_sl[(size_t)NBW * WIN * WIN];
__device__ bf16 g_yh[(size_t)MTOK * DMODEL];
__device__ bf16 g_yl[(size_t)MTOK * DMODEL];
__device__ bf16 g_wth[4][(size_t)DMODEL * DMODEL];  // W^T splits (q,k,v,o)
__device__ bf16 g_wtl[4][(size_t)DMODEL * DMODEL];

// ---------------- primitives ----------------
__device__ __forceinline__ void mma16816(float* c, const uint32_t* a,
                                         const uint32_t* b) {
    asm volatile(
        "mma.sync.aligned.m16n8k16.row.col.f32.bf16.bf16.f32 "
        "{%0,%1,%2,%3}, {%4,%5,%6,%7}, {%8,%9}, {%0,%1,%2,%3};"
        : "+f"(c[0]), "+f"(c[1]), "+f"(c[2]), "+f"(c[3])
        : "r"(a[0]), "r"(a[1]), "r"(a[2]), "r"(a[3]), "r"(b[0]), "r"(b[1]));
}

__device__ __forceinline__ void ldsm4(uint32_t* r, uint32_t addr) {
    asm volatile(
        "ldmatrix.sync.aligned.m8n8.x4.shared.b16 {%0,%1,%2,%3}, [%4];"
        : "=r"(r[0]), "=r"(r[1]), "=r"(r[2]), "=r"(r[3])
        : "r"(addr));
}

__device__ __forceinline__ void cpa16(uint32_t s, const void* g) {
    asm volatile("cp.async.cg.shared.global [%0], [%1], 16;"
                 :: "r"(s), "l"(g) : "memory");
}
__device__ __forceinline__ void cpa_commit() {
    asm volatile("cp.async.commit_group;" ::: "memory");
}
__device__ __forceinline__ void cpa_wait1() {
    asm volatile("cp.async.wait_group 1;" ::: "memory");
}
__device__ __forceinline__ void cpa_wait0() {
    asm volatile("cp.async.wait_group 0;" ::: "memory");
}

__device__ __forceinline__ bf16 hi_of(float v) { return __float2bfloat16_rn(v); }
__device__ __forceinline__ bf16 lo_of(float v, bf16 h) {
    return __float2bfloat16_rn(v - __bfloat162float(h));
}

// ---------------- bf16x3 GEMM core (3-stage cp.async, 1 sync/tile) ---------
// C = scale * (A @ Bt^T) + bias. A=[m,k] k-major split hi/lo, Bt=[n,k]
// k-major split hi/lo. Block 128x128x32, 256 threads.
// om=0: write fp32 C. om=1: write bf16 hi/lo pair (Ch, Cl).
#define SROW 40
#define MATB (128 * SROW * 2)     // bytes per matrix per stage (10240)
#define STB (4 * MATB)            // bytes per stage (40960)
#define GSMEM (3 * STB)           // 122880 bytes dynamic smem

__device__ __forceinline__ void gemm_core(
    const bf16* __restrict__ Ah, const bf16* __restrict__ Al, int lda,
    const bf16* __restrict__ Bh, const bf16* __restrict__ Bl, int ldb,
    const float* __restrict__ bias, float scale,
    float* __restrict__ C, bf16* __restrict__ Ch, bf16* __restrict__ Cl,
    int ldc, int K, int by, int bx, int om)
{
    extern __shared__ __align__(16) char smbuf[];
    const uint32_t smu = (uint32_t)__cvta_generic_to_shared(smbuf);

    const int t = threadIdx.x;
    const int lane = t & 31;
    const int warp = t >> 5;
    const int wm = warp >> 1;     // 0..3 -> 32-row slabs
    const int wn = warp & 1;      // 0..1 -> 64-col slabs

    const int grow = t >> 2;            // 0..63
    const int gcg = (t & 3) * 8;        // 0,8,16,24
    const bf16* pAh = Ah + (size_t)(by + grow) * lda + gcg;
    const bf16* pAl = Al + (size_t)(by + grow) * lda + gcg;
    const bf16* pBh = Bh + (size_t)(bx + grow) * ldb + gcg;
    const bf16* pBl = Bl + (size_t)(bx + grow) * ldb + gcg;
    const size_t astep = (size_t)64 * lda;
    const size_t bstep = (size_t)64 * ldb;

    const uint32_t soffB = (uint32_t)(grow * SROW + gcg) * 2;
    const uint32_t r2 = 64 * SROW * 2;

    // ldmatrix lane mapping
    const int lg = lane & 7;
    const int sel = lane >> 3;
    const int radd = (sel & 1) * 8;
    const int cadd = (sel >> 1) * 8;
    const int radd_b = (sel >> 1) * 8;
    const int cadd_b = (sel & 1) * 8;

    float acc[2][8][4];
#pragma unroll
    for (int i = 0; i < 2; i++)
#pragma unroll
        for (int j = 0; j < 8; j++)
#pragma unroll
            for (int q = 0; q < 4; q++) acc[i][j][q] = 0.f;

#define ISSUE(kt, st)                                                     \
    {                                                                     \
        const size_t ko = (size_t)(kt) * 32;                              \
        const uint32_t d = smu + (st) * STB + soffB;                      \
        cpa16(d, pAh + ko);                                               \
        cpa16(d + r2, pAh + astep + ko);                                  \
        cpa16(d + MATB, pAl + ko);                                        \
        cpa16(d + MATB + r2, pAl + astep + ko);                           \
        cpa16(d + 2 * MATB, pBh + ko);                                    \
        cpa16(d + 2 * MATB + r2, pBh + bstep + ko);                       \
        cpa16(d + 3 * MATB, pBl + ko);                                    \
        cpa16(d + 3 * MATB + r2, pBl + bstep + ko);                       \
        cpa_commit();                                                     \
    }

    const int nt = K / 32;              // >= 8 at all call sites
    ISSUE(0, 0);
    ISSUE(1, 1);

    int cur = 0;                        // stage of tile kt
    for (int kt = 0; kt < nt; kt++) {
        if (kt < nt - 1) cpa_wait1(); else cpa_wait0();
        __syncthreads();
        // refill the stage that was consumed at iteration kt-1
        if (kt + 2 < nt) {
            int s2 = cur + 2; if (s2 >= 3) s2 -= 3;
            ISSUE(kt + 2, s2);
        }

        const uint32_t bAh = smu + cur * STB;
        const uint32_t bAl = bAh + MATB;
        const uint32_t bBh = bAh + 2 * MATB;
        const uint32_t bBl = bAh + 3 * MATB;

#pragma unroll
        for (int kk = 0; kk < 32; kk += 16) {
            uint32_t ah[2][4], al[2][4], bh[4][4], bl[4][4];
#pragma unroll
            for (int i = 0; i < 2; i++) {
                const uint32_t off =
                    ((wm * 32 + i * 16 + radd + lg) * SROW + kk + cadd) * 2;
                ldsm4(ah[i], bAh + off);
                ldsm4(al[i], bAl + off);
            }
#pragma unroll
            for (int jp = 0; jp < 4; jp++) {
                const uint32_t off =
                    ((wn * 64 + jp * 16 + radd_b + lg) * SROW + kk + cadd_b) * 2;
                ldsm4(bh[jp], bBh + off);
                ldsm4(bl[jp], bBl + off);
            }
#pragma unroll
            for (int i = 0; i < 2; i++)
#pragma unroll
                for (int j = 0; j < 8; j++) {
                    const uint32_t* bhp = &bh[j >> 1][(j & 1) * 2];
                    const uint32_t* blp = &bl[j >> 1][(j & 1) * 2];
                    mma16816(acc[i][j], ah[i], bhp);
                    mma16816(acc[i][j], al[i], bhp);
                    mma16816(acc[i][j], ah[i], blp);
                }
        }
        if (++cur == 3) cur = 0;
    }
#undef ISSUE

    // epilogue
    const int lrow = lane >> 2;
    const int lcol = (lane & 3) * 2;
#pragma unroll
    for (int i = 0; i < 2; i++) {
        const int r0 = by + wm * 32 + i * 16 + lrow;
#pragma unroll
        for (int j = 0; j < 8; j++) {
            const int c = bx + wn * 64 + j * 8 + lcol;
            float b0 = 0.f, b1 = 0.f;
            if (bias) { b0 = bias[c]; b1 = bias[c + 1]; }
            const float v00 = acc[i][j][0] * scale + b0;
            const float v01 = acc[i][j][1] * scale + b1;
            const float v10 = acc[i][j][2] * scale + b0;
            const float v11 = acc[i][j][3] * scale + b1;
            if (om == 0) {
                *(float2*)&C[(size_t)r0 * ldc + c] = make_float2(v00, v01);
                *(float2*)&C[(size_t)(r0 + 8) * ldc + c] = make_float2(v10, v11);
            } else {
                const bf16 h00 = hi_of(v00), h01 = hi_of(v01);
                const bf16 h10 = hi_of(v10), h11 = hi_of(v11);
                __nv_bfloat162 hp0{h00, h01}, hp1{h10, h11};
                __nv_bfloat162 lp0{lo_of(v00, h00), lo_of(v01, h01)};
                __nv_bfloat162 lp1{lo_of(v10, h10), lo_of(v11, h11)};
                *(__nv_bfloat162*)&Ch[(size_t)r0 * ldc + c] = hp0;
                *(__nv_bfloat162*)&Ch[(size_t)(r0 + 8) * ldc + c] = hp1;
                *(__nv_bfloat162*)&Cl[(size_t)r0 * ldc + c] = lp0;
                *(__nv_bfloat162*)&Cl[(size_t)(r0 + 8) * ldc + c] = lp1;
            }
        }
    }
}

// ---------------- GEMM wrappers ----------------
// Merged Q/K/V projection: grid (24, 128). bx/8 selects weight+output.
__global__ __launch_bounds__(256) void gemm_qkv(
    const bf16* __restrict__ xh, const bf16* __restrict__ xl,
    const bf16* __restrict__ wh, const bf16* __restrict__ wl,   // g_wth/g_wtl base
    const float* __restrict__ bq, const float* __restrict__ bk,
    const float* __restrict__ bv,
    bf16* __restrict__ qh, bf16* __restrict__ ql,
    bf16* __restrict__ kh, bf16* __restrict__ kl,
    float* __restrict__ v)
{
    const int idx = blockIdx.x >> 3;          // 0=q, 1=k, 2=v
    const int bx = (blockIdx.x & 7) * 128;
    const size_t woff = (size_t)idx * DMODEL * DMODEL;
    const float* bias = (idx == 0) ? bq : (idx == 1) ? bk : bv;

    if (idx == 0)
        gemm_core(xh, xl, DMODEL, wh + woff, wl + woff, DMODEL, bias, 1.f,
                  nullptr, qh, ql, DMODEL, DMODEL, blockIdx.y * 128, bx, 1);
    else if (idx == 1)
        gemm_core(xh, xl, DMODEL, wh + woff, wl + woff, DMODEL, bias, 1.f,
                  nullptr, kh, kl, DMODEL, DMODEL, blockIdx.y * 128, bx, 1);
    else
        gemm_core(xh, xl, DMODEL, wh + woff, wl + woff, DMODEL, bias, 1.f,
                  v, nullptr, nullptr, DMODEL, DMODEL, blockIdx.y * 128, bx, 0);
}

__global__ __launch_bounds__(256) void gemm_proj_f(
    const bf16* __restrict__ Ah, const bf16* __restrict__ Al,
    const bf16* __restrict__ Bth, const bf16* __restrict__ Btl,
    const float* __restrict__ bias, float* __restrict__ C)
{
    gemm_core(Ah, Al, DMODEL, Bth, Btl, DMODEL, bias, 1.f,
              C, nullptr, nullptr, DMODEL, DMODEL,
              blockIdx.y * 128, blockIdx.x * 128, 0);
}

__global__ __launch_bounds__(256) void gemm_scores(
    const bf16* __restrict__ qh, const bf16* __restrict__ ql,
    const bf16* __restrict__ kh, const bf16* __restrict__ kl,
    float* __restrict__ s)
{
    const int z = blockIdx.z;
    const int b = z / NWIN;
    const int w = z - b * NWIN;
    const size_t off = ((size_t)b * SEQ + 128 * w) * DMODEL;
    gemm_core(qh + off, ql + off, DMODEL, kh + off, kl + off, DMODEL,
              nullptr, 0.125f, s + (size_t)z * WIN * WIN, nullptr, nullptr,
              WIN, DMODEL, blockIdx.y * 128, blockIdx.x * 128, 0);
}

__global__ __launch_bounds__(256) void gemm_pv(
    const bf16* __restrict__ sh, const bf16* __restrict__ sl,
    const bf16* __restrict__ vth, const bf16* __restrict__ vtl,
    float* __restrict__ ow)
{
    const int z = blockIdx.z;
    const int b = z / NWIN;
    const int w = z - b * NWIN;
    const size_t aoff = (size_t)z * WIN * WIN;
    const size_t boff = (size_t)b * DMODEL * SEQ + 128 * w;
    gemm_core(sh + aoff, sl + aoff, WIN, vth + boff, vtl + boff, SEQ,
              nullptr, 1.f, ow + (size_t)z * WIN * DMODEL, nullptr, nullptr,
              DMODEL, WIN, blockIdx.y * 128, blockIdx.x * 128, 0);
}

// ---------------- split kernels ----------------
__global__ __launch_bounds__(256) void split_plain(
    const float* __restrict__ src, bf16* __restrict__ h,
    bf16* __restrict__ l, int n4)
{
    for (int i = blockIdx.x * 256 + threadIdx.x; i < n4;
         i += gridDim.x * 256) {
        float4 v = ((const float4*)src)[i];
        bf16 hx = hi_of(v.x), hy = hi_of(v.y), hz = hi_of(v.z), hw = hi_of(v.w);
        __nv_bfloat162 h01{hx, hy}, h23{hz, hw};
        __nv_bfloat162 l01{lo_of(v.x, hx), lo_of(v.y, hy)};
        __nv_bfloat162 l23{lo_of(v.z, hz), lo_of(v.w, hw)};
        ((__nv_bfloat162*)h)[2 * i]     = h01;
        ((__nv_bfloat162*)h)[2 * i + 1] = h23;
        ((__nv_bfloat162*)l)[2 * i]     = l01;
        ((__nv_bfloat162*)l)[2 * i + 1] = l23;
    }
}

// transpose + split: src [R][Cc] fp32 -> dst [Cc][R] bf16 hi/lo
__global__ __launch_bounds__(256) void split_T(
    const float* __restrict__ src, bf16* __restrict__ dh,
    bf16* __restrict__ dl, int R, int Cc, size_t sStride, size_t dStride)
{
    __shared__ float tile[32][33];
    const float* S = src + blockIdx.z * sStride;
    bf16* H = dh + blockIdx.z * dStride;
    bf16* L = dl + blockIdx.z * dStride;

    const int c0 = blockIdx.x * 32;
    const int r0 = blockIdx.y * 32;
    const int tx = threadIdx.x & 31;
    const int ty = threadIdx.x >> 5;

#pragma unroll
    for (int k = 0; k < 4; k++)
        tile[ty + 8 * k][tx] = S[(size_t)(r0 + ty + 8 * k) * Cc + c0 + tx];
    __syncthreads();

#pragma unroll
    for (int k = 0; k < 4; k++) {
        const float v = tile[tx][ty + 8 * k];
        const bf16 hv = hi_of(v);
        const bf16 lv = lo_of(v, hv);
        const size_t o = (size_t)(c0 + ty + 8 * k) * R + r0 + tx;
        H[o] = hv;
        L[o] = lv;
    }
}

// ---------------- softmax + split (warp per 256-wide row) ----------------
__global__ __launch_bounds__(256) void win_softmax_split(
    const float* __restrict__ s, bf16* __restrict__ sh, bf16* __restrict__ sl)
{
    const int row = blockIdx.x * 8 + (threadIdx.x >> 5);
    const int lane = threadIdx.x & 31;
    const float* r = s + (size_t)row * WIN;

    float v[8];
    float m = -1e30f;
#pragma unroll
    for (int j = 0; j < 8; j++) {
        v[j] = r[lane + 32 * j];
        m = fmaxf(m, v[j]);
    }
#pragma unroll
    for (int o = 16; o > 0; o >>= 1)
        m = fmaxf(m, __shfl_xor_sync(0xffffffffu, m, o));

    float sum = 0.f;
#pragma unroll
    for (int j = 0; j < 8; j++) { v[j] = expf(v[j] - m); sum += v[j]; }
#pragma unroll
    for (int o = 16; o > 0; o >>= 1)
        sum += __shfl_xor_sync(0xffffffffu, sum, o);
    const float inv = 1.f / sum;

#pragma unroll
    for (int j = 0; j < 8; j++) {
        const float p = v[j] * inv;
        const bf16 h = hi_of(p);
        const size_t o = (size_t)row * WIN + lane + 32 * j;
        sh[o] = h;
        sl[o] = lo_of(p, h);
    }
}

// ---------------- combine + split ----------------
__global__ __launch_bounds__(256) void combine_split(
    const float* __restrict__ ow, bf16* __restrict__ yh, bf16* __restrict__ yl)
{
    const int idx = blockIdx.x * 256 + threadIdx.x;
    const int c = idx & (DMODEL - 1);
    const int bt = idx >> 10;
    const int t = bt & (SEQ - 1);
    const int b = bt >> 12;

    const int w1 = t >> 7;
    float val = 0.f, cnt = 0.f;
#pragma unroll
    for (int dw = -1; dw <= 0; dw++) {
        const int w = w1 + dw;
        if (w < 0 || w >= NWIN) continue;
        const int pos = t - 128 * w;
        if (pos < 0 || pos >= WIN) continue;
        val += ow[(((size_t)(b * NWIN + w)) * WIN + pos) * DMODEL + c];
        cnt += 1.f;
    }
    const float y = val / cnt;
    const bf16 h = hi_of(y);
    yh[idx] = h;
    yl[idx] = lo_of(y, h);
}

// ---------------- launch ----------------
extern "C" void kernel_launch(void* const* d_in, const int* in_sizes, int n_in,
                              void* d_out, int out_size)
{
    const float* x  = (const float*)d_in[0];
    const float* Wq = (const float*)d_in[1];
    const float* bq = (const float*)d_in[2];
    const float* Wk = (const float*)d_in[3];
    const float* bk = (const float*)d_in[4];
    const float* Wv = (const float*)d_in[5];
    const float* bv = (const float*)d_in[6];
    const float* Wo = (const float*)d_in[7];
    const float* bo = (const float*)d_in[8];
    float* out = (float*)d_out;

    float *vb, *sb, *owb;
    cudaGetSymbolAddress((void**)&vb, g_v);
    cudaGetSymbolAddress((void**)&sb, g_s);
    cudaGetSymbolAddress((void**)&owb, g_ow);
    bf16 *xh, *xl, *qh, *ql, *kh, *kl, *vth, *vtl, *sh, *sl, *yh, *yl;
    bf16 (*wth)[DMODEL * DMODEL], (*wtl)[DMODEL * DMODEL];
    cudaGetSymbolAddress((void**)&xh, g_xh);
    cudaGetSymbolAddress((void**)&xl, g_xl);
    cudaGetSymbolAddress((void**)&qh, g_qh);
    cudaGetSymbolAddress((void**)&ql, g_ql);
    cudaGetSymbolAddress((void**)&kh, g_kh);
    cudaGetSymbolAddress((void**)&kl, g_kl);
    cudaGetSymbolAddress((void**)&vth, g_vth);
    cudaGetSymbolAddress((void**)&vtl, g_vtl);
    cudaGetSymbolAddress((void**)&sh, g_sh);
    cudaGetSymbolAddress((void**)&sl, g_sl);
    cudaGetSymbolAddress((void**)&yh, g_yh);
    cudaGetSymbolAddress((void**)&yl, g_yl);
    cudaGetSymbolAddress((void**)&wth, g_wth);
    cudaGetSymbolAddress((void**)&wtl, g_wtl);

    cudaFuncSetAttribute(gemm_qkv,
        cudaFuncAttributeMaxDynamicSharedMemorySize, GSMEM);
    cudaFuncSetAttribute(gemm_proj_f,
        cudaFuncAttributeMaxDynamicSharedMemorySize, GSMEM);
    cudaFuncSetAttribute(gemm_scores,
        cudaFuncAttributeMaxDynamicSharedMemorySize, GSMEM);
    cudaFuncSetAttribute(gemm_pv,
        cudaFuncAttributeMaxDynamicSharedMemorySize, GSMEM);

    // weight transpose+split (W[K][N] -> Wt[N][K])
    const dim3 wtg(32, 32, 1);
    split_T<<<wtg, 256>>>(Wq, wth[0], wtl[0], DMODEL, DMODEL, 0, 0);
    split_T<<<wtg, 256>>>(Wk, wth[1], wtl[1], DMODEL, DMODEL, 0, 0);
    split_T<<<wtg, 256>>>(Wv, wth[2], wtl[2], DMODEL, DMODEL, 0, 0);
    split_T<<<wtg, 256>>>(Wo, wth[3], wtl[3], DMODEL, DMODEL, 0, 0);

    split_plain<<<2048, 256>>>(x, xh, xl, MTOK * DMODEL / 4);

    // merged q/k/v projections: grid (3*8, 128)
    gemm_qkv<<<dim3(24, MTOK / 128), 256, GSMEM>>>(
        xh, xl, (const bf16*)wth, (const bf16*)wtl,
        bq, bk, bv, qh, ql, kh, kl, vb);

    split_T<<<dim3(32, SEQ / 32, BATCH), 256>>>(
        vb, vth, vtl, SEQ, DMODEL,
        (size_t)SEQ * DMODEL, (size_t)SEQ * DMODEL);

    gemm_scores<<<dim3(2, 2, NBW), 256, GSMEM>>>(qh, ql, kh, kl, sb);

    win_softmax_split<<<(NBW * WIN) / 8, 256>>>(sb, sh, sl);

    gemm_pv<<<dim3(DMODEL / 128, 2, NBW), 256, GSMEM>>>(sh, sl, vth, vtl, owb);

    combine_split<<<(MTOK * DMODEL) / 256, 256>>>(owb, yh, yl);

    gemm_proj_f<<<dim3(DMODEL / 128, MTOK / 128), 256, GSMEM>>>(
        yh, yl, wth[3], wtl[3], bo, out);
}

// round 12
// speedup vs baseline: 1.0826x; 1.0826x over previous
#include <cuda_runtime.h>
#include <cuda_bf16.h>
#include <cstdint>

// ---------------- problem constants ----------------
#define BATCH 4
#define SEQ 4096
#define DMODEL 1024
#define WIN 256
#define NWIN 31              // window starts 0,128,...,3840
#define NBW (BATCH * NWIN)   // 124
#define MTOK (BATCH * SEQ)   // 16384

typedef __nv_bfloat16 bf16;

// ---------------- scratch (static device globals, no allocs) ----------------
__device__ float g_v[(size_t)MTOK * DMODEL];
__device__ float g_s[(size_t)NBW * WIN * WIN];
__device__ float g_ow[(size_t)NBW * WIN * DMODEL];

__device__ bf16 g_xh[(size_t)MTOK * DMODEL];
__device__ bf16 g_xl[(size_t)MTOK * DMODEL];
__device__ bf16 g_qh[(size_t)MTOK * DMODEL];
__device__ bf16 g_ql[(size_t)MTOK * DMODEL];
__device__ bf16 g_kh[(size_t)MTOK * DMODEL];
__device__ bf16 g_kl[(size_t)MTOK * DMODEL];
__device__ bf16 g_vth[(size_t)MTOK * DMODEL];   // per-batch V^T [1024][4096]
__device__ bf16 g_vtl[(size_t)MTOK * DMODEL];
__device__ bf16 g_sh[(size_t)NBW * WIN * WIN];
__device__ bf16 g_sl[(size_t)NBW * WIN * WIN];
__device__ bf16 g_yh[(size_t)MTOK * DMODEL];
__device__ bf16 g_yl[(size_t)MTOK * DMODEL];
__device__ bf16 g_wth[4][(size_t)DMODEL * DMODEL];  // W^T splits (q,k,v,o)
__device__ bf16 g_wtl[4][(size_t)DMODEL * DMODEL];

// ---------------- primitives ----------------
__device__ __forceinline__ void mma16816(float* c, const uint32_t* a,
                                         const uint32_t* b) {
    asm volatile(
        "mma.sync.aligned.m16n8k16.row.col.f32.bf16.bf16.f32 "
        "{%0,%1,%2,%3}, {%4,%5,%6,%7}, {%8,%9}, {%0,%1,%2,%3};"
        : "+f"(c[0]), "+f"(c[1]), "+f"(c[2]), "+f"(c[3])
        : "r"(a[0]), "r"(a[1]), "r"(a[2]), "r"(a[3]), "r"(b[0]), "r"(b[1]));
}

__device__ __forceinline__ void ldsm4(uint32_t* r, uint32_t addr) {
    asm volatile(
        "ldmatrix.sync.aligned.m8n8.x4.shared.b16 {%0,%1,%2,%3}, [%4];"
        : "=r"(r[0]), "=r"(r[1]), "=r"(r[2]), "=r"(r[3])
        : "r"(addr));
}

__device__ __forceinline__ void cpa16(uint32_t s, const void* g) {
    asm volatile("cp.async.cg.shared.global [%0], [%1], 16;"
                 :: "r"(s), "l"(g) : "memory");
}
__device__ __forceinline__ void cpa_commit() {
    asm volatile("cp.async.commit_group;" ::: "memory");
}
__device__ __forceinline__ void cpa_wait1() {
    asm volatile("cp.async.wait_group 1;" ::: "memory");
}
__device__ __forceinline__ void cpa_wait0() {
    asm volatile("cp.async.wait_group 0;" ::: "memory");
}

__device__ __forceinline__ bf16 hi_of(float v) { return __float2bfloat16_rn(v); }
__device__ __forceinline__ bf16 lo_of(float v, bf16 h) {
    return __float2bfloat16_rn(v - __bfloat162float(h));
}

// ---------------- bf16x3 GEMM core (2-stage cp.async, 2 CTAs/SM) ----------
// C = scale * (A @ Bt^T) + bias. A=[m,k] k-major split hi/lo, Bt=[n,k]
// k-major split hi/lo. Block 128x128x32, 256 threads.
// om=0: write fp32 C. om=1: write bf16 hi/lo pair (Ch, Cl).
#define SROW 40
#define MATB (128 * SROW * 2)     // bytes per matrix per stage (10240)
#define STB (4 * MATB)            // bytes per stage (40960)
#define GSMEM (2 * STB)           // 81920 bytes dynamic smem -> 2 CTAs/SM

__device__ __forceinline__ void gemm_core(
    const bf16* __restrict__ Ah, const bf16* __restrict__ Al, int lda,
    const bf16* __restrict__ Bh, const bf16* __restrict__ Bl, int ldb,
    const float* __restrict__ bias, float scale,
    float* __restrict__ C, bf16* __restrict__ Ch, bf16* __restrict__ Cl,
    int ldc, int K, int by, int bx, int om)
{
    extern __shared__ __align__(16) char smbuf[];
    const uint32_t smu = (uint32_t)__cvta_generic_to_shared(smbuf);

    const int t = threadIdx.x;
    const int lane = t & 31;
    const int warp = t >> 5;
    const int wm = warp >> 1;     // 0..3 -> 32-row slabs
    const int wn = warp & 1;      // 0..1 -> 64-col slabs

    const int grow = t >> 2;            // 0..63
    const int gcg = (t & 3) * 8;        // 0,8,16,24
    const bf16* pAh = Ah + (size_t)(by + grow) * lda + gcg;
    const bf16* pAl = Al + (size_t)(by + grow) * lda + gcg;
    const bf16* pBh = Bh + (size_t)(bx + grow) * ldb + gcg;
    const bf16* pBl = Bl + (size_t)(bx + grow) * ldb + gcg;
    const size_t astep = (size_t)64 * lda;
    const size_t bstep = (size_t)64 * ldb;

    const uint32_t soffB = (uint32_t)(grow * SROW + gcg) * 2;
    const uint32_t r2 = 64 * SROW * 2;

    // ldmatrix lane mapping
    const int lg = lane & 7;
    const int sel = lane >> 3;
    const int radd = (sel & 1) * 8;
    const int cadd = (sel >> 1) * 8;
    const int radd_b = (sel >> 1) * 8;
    const int cadd_b = (sel & 1) * 8;

    float acc[2][8][4];
#pragma unroll
    for (int i = 0; i < 2; i++)
#pragma unroll
        for (int j = 0; j < 8; j++)
#pragma unroll
            for (int q = 0; q < 4; q++) acc[i][j][q] = 0.f;

#define ISSUE(kt, st)                                                     \
    {                                                                     \
        const size_t ko = (size_t)(kt) * 32;                              \
        const uint32_t d = smu + (st) * STB + soffB;                      \
        cpa16(d, pAh + ko);                                               \
        cpa16(d + r2, pAh + astep + ko);                                  \
        cpa16(d + MATB, pAl + ko);                                        \
        cpa16(d + MATB + r2, pAl + astep + ko);                           \
        cpa16(d + 2 * MATB, pBh + ko);                                    \
        cpa16(d + 2 * MATB + r2, pBh + bstep + ko);                       \
        cpa16(d + 3 * MATB, pBl + ko);                                    \
        cpa16(d + 3 * MATB + r2, pBl + bstep + ko);                       \
    }

    const int nt = K / 32;
    ISSUE(0, 0);
    cpa_commit();

    for (int kt = 0; kt < nt; kt++) {
        const int cur = kt & 1;
        if (kt + 1 < nt) {
            ISSUE(kt + 1, cur ^ 1);
            cpa_commit();
            cpa_wait1();
        } else {
            cpa_wait0();
        }
        __syncthreads();

        const uint32_t bAh = smu + cur * STB;
        const uint32_t bAl = bAh + MATB;
        const uint32_t bBh = bAh + 2 * MATB;
        const uint32_t bBl = bAh + 3 * MATB;

#pragma unroll
        for (int kk = 0; kk < 32; kk += 16) {
            uint32_t ah[2][4], al[2][4], bh[4][4], bl[4][4];
#pragma unroll
            for (int i = 0; i < 2; i++) {
                const uint32_t off =
                    ((wm * 32 + i * 16 + radd + lg) * SROW + kk + cadd) * 2;
                ldsm4(ah[i], bAh + off);
                ldsm4(al[i], bAl + off);
            }
#pragma unroll
            for (int jp = 0; jp < 4; jp++) {
                const uint32_t off =
                    ((wn * 64 + jp * 16 + radd_b + lg) * SROW + kk + cadd_b) * 2;
                ldsm4(bh[jp], bBh + off);
                ldsm4(bl[jp], bBl + off);
            }
#pragma unroll
            for (int i = 0; i < 2; i++)
#pragma unroll
                for (int j = 0; j < 8; j++) {
                    const uint32_t* bhp = &bh[j >> 1][(j & 1) * 2];
                    const uint32_t* blp = &bl[j >> 1][(j & 1) * 2];
                    mma16816(acc[i][j], ah[i], bhp);
                    mma16816(acc[i][j], al[i], bhp);
                    mma16816(acc[i][j], ah[i], blp);
                }
        }
        __syncthreads();
    }
#undef ISSUE

    // epilogue
    const int lrow = lane >> 2;
    const int lcol = (lane & 3) * 2;
#pragma unroll
    for (int i = 0; i < 2; i++) {
        const int r0 = by + wm * 32 + i * 16 + lrow;
#pragma unroll
        for (int j = 0; j < 8; j++) {
            const int c = bx + wn * 64 + j * 8 + lcol;
            float b0 = 0.f, b1 = 0.f;
            if (bias) { b0 = bias[c]; b1 = bias[c + 1]; }
            const float v00 = acc[i][j][0] * scale + b0;
            const float v01 = acc[i][j][1] * scale + b1;
            const float v10 = acc[i][j][2] * scale + b0;
            const float v11 = acc[i][j][3] * scale + b1;
            if (om == 0) {
                *(float2*)&C[(size_t)r0 * ldc + c] = make_float2(v00, v01);
                *(float2*)&C[(size_t)(r0 + 8) * ldc + c] = make_float2(v10, v11);
            } else {
                const bf16 h00 = hi_of(v00), h01 = hi_of(v01);
                const bf16 h10 = hi_of(v10), h11 = hi_of(v11);
                __nv_bfloat162 hp0{h00, h01}, hp1{h10, h11};
                __nv_bfloat162 lp0{lo_of(v00, h00), lo_of(v01, h01)};
                __nv_bfloat162 lp1{lo_of(v10, h10), lo_of(v11, h11)};
                *(__nv_bfloat162*)&Ch[(size_t)r0 * ldc + c] = hp0;
                *(__nv_bfloat162*)&Ch[(size_t)(r0 + 8) * ldc + c] = hp1;
                *(__nv_bfloat162*)&Cl[(size_t)r0 * ldc + c] = lp0;
                *(__nv_bfloat162*)&Cl[(size_t)(r0 + 8) * ldc + c] = lp1;
            }
        }
    }
}

// ---------------- GEMM wrappers ----------------
// Merged Q/K/V projection: grid (24, 128). blockIdx.x>>3 selects matrix.
__global__ __launch_bounds__(256) void gemm_qkv(
    const bf16* __restrict__ xh, const bf16* __restrict__ xl,
    const bf16* __restrict__ wh, const bf16* __restrict__ wl,
    const float* __restrict__ bq, const float* __restrict__ bk,
    const float* __restrict__ bv,
    bf16* __restrict__ qh, bf16* __restrict__ ql,
    bf16* __restrict__ kh, bf16* __restrict__ kl,
    float* __restrict__ v)
{
    const int idx = blockIdx.x >> 3;          // 0=q, 1=k, 2=v
    const int bx = (blockIdx.x & 7) * 128;
    const size_t woff = (size_t)idx * DMODEL * DMODEL;
    if (idx == 0)
        gemm_core(xh, xl, DMODEL, wh + woff, wl + woff, DMODEL, bq, 1.f,
                  nullptr, qh, ql, DMODEL, DMODEL, blockIdx.y * 128, bx, 1);
    else if (idx == 1)
        gemm_core(xh, xl, DMODEL, wh + woff, wl + woff, DMODEL, bk, 1.f,
                  nullptr, kh, kl, DMODEL, DMODEL, blockIdx.y * 128, bx, 1);
    else
        gemm_core(xh, xl, DMODEL, wh + woff, wl + woff, DMODEL, bv, 1.f,
                  v, nullptr, nullptr, DMODEL, DMODEL, blockIdx.y * 128, bx, 0);
}

__global__ __launch_bounds__(256) void gemm_proj_f(
    const bf16* __restrict__ Ah, const bf16* __restrict__ Al,
    const bf16* __restrict__ Bth, const bf16* __restrict__ Btl,
    const float* __restrict__ bias, float* __restrict__ C)
{
    gemm_core(Ah, Al, DMODEL, Bth, Btl, DMODEL, bias, 1.f,
              C, nullptr, nullptr, DMODEL, DMODEL,
              blockIdx.y * 128, blockIdx.x * 128, 0);
}

__global__ __launch_bounds__(256) void gemm_scores(
    const bf16* __restrict__ qh, const bf16* __restrict__ ql,
    const bf16* __restrict__ kh, const bf16* __restrict__ kl,
    float* __restrict__ s)
{
    const int z = blockIdx.z;
    const int b = z / NWIN;
    const int w = z - b * NWIN;
    const size_t off = ((size_t)b * SEQ + 128 * w) * DMODEL;
    gemm_core(qh + off, ql + off, DMODEL, kh + off, kl + off, DMODEL,
              nullptr, 0.125f, s + (size_t)z * WIN * WIN, nullptr, nullptr,
              WIN, DMODEL, blockIdx.y * 128, blockIdx.x * 128, 0);
}

__global__ __launch_bounds__(256) void gemm_pv(
    const bf16* __restrict__ sh, const bf16* __restrict__ sl,
    const bf16* __restrict__ vth, const bf16* __restrict__ vtl,
    float* __restrict__ ow)
{
    const int z = blockIdx.z;
    const int b = z / NWIN;
    const int w = z - b * NWIN;
    const size_t aoff = (size_t)z * WIN * WIN;
    const size_t boff = (size_t)b * DMODEL * SEQ + 128 * w;
    gemm_core(sh + aoff, sl + aoff, WIN, vth + boff, vtl + boff, SEQ,
              nullptr, 1.f, ow + (size_t)z * WIN * DMODEL, nullptr, nullptr,
              DMODEL, WIN, blockIdx.y * 128, blockIdx.x * 128, 0);
}

// ---------------- split kernels ----------------
__global__ __launch_bounds__(256) void split_plain(
    const float* __restrict__ src, bf16* __restrict__ h,
    bf16* __restrict__ l, int n4)
{
    for (int i = blockIdx.x * 256 + threadIdx.x; i < n4;
         i += gridDim.x * 256) {
        float4 v = ((const float4*)src)[i];
        bf16 hx = hi_of(v.x), hy = hi_of(v.y), hz = hi_of(v.z), hw = hi_of(v.w);
        __nv_bfloat162 h01{hx, hy}, h23{hz, hw};
        __nv_bfloat162 l01{lo_of(v.x, hx), lo_of(v.y, hy)};
        __nv_bfloat162 l23{lo_of(v.z, hz), lo_of(v.w, hw)};
        ((__nv_bfloat162*)h)[2 * i]     = h01;
        ((__nv_bfloat162*)h)[2 * i + 1] = h23;
        ((__nv_bfloat162*)l)[2 * i]     = l01;
        ((__nv_bfloat162*)l)[2 * i + 1] = l23;
    }
}

// transpose + split: src [R][Cc] fp32 -> dst [Cc][R] bf16 hi/lo
__global__ __launch_bounds__(256) void split_T(
    const float* __restrict__ src, bf16* __restrict__ dh,
    bf16* __restrict__ dl, int R, int Cc, size_t sStride, size_t dStride)
{
    __shared__ float tile[32][33];
    const float* S = src + blockIdx.z * sStride;
    bf16* H = dh + blockIdx.z * dStride;
    bf16* L = dl + blockIdx.z * dStride;

    const int c0 = blockIdx.x * 32;
    const int r0 = blockIdx.y * 32;
    const int tx = threadIdx.x & 31;
    const int ty = threadIdx.x >> 5;

#pragma unroll
    for (int k = 0; k < 4; k++)
        tile[ty + 8 * k][tx] = S[(size_t)(r0 + ty + 8 * k) * Cc + c0 + tx];
    __syncthreads();

#pragma unroll
    for (int k = 0; k < 4; k++) {
        const float v = tile[tx][ty + 8 * k];
        const bf16 hv = hi_of(v);
        const bf16 lv = lo_of(v, hv);
        const size_t o = (size_t)(c0 + ty + 8 * k) * R + r0 + tx;
        H[o] = hv;
        L[o] = lv;
    }
}

// ---------------- softmax + split (warp per 256-wide row) ----------------
__global__ __launch_bounds__(256) void win_softmax_split(
    const float* __restrict__ s, bf16* __restrict__ sh, bf16* __restrict__ sl)
{
    const int row = blockIdx.x * 8 + (threadIdx.x >> 5);
    const int lane = threadIdx.x & 31;
    const float* r = s + (size_t)row * WIN;

    float v[8];
    float m = -1e30f;
#pragma unroll
    for (int j = 0; j < 8; j++) {
        v[j] = r[lane + 32 * j];
        m = fmaxf(m, v[j]);
    }
#pragma unroll
    for (int o = 16; o > 0; o >>= 1)
        m = fmaxf(m, __shfl_xor_sync(0xffffffffu, m, o));

    float sum = 0.f;
#pragma unroll
    for (int j = 0; j < 8; j++) { v[j] = expf(v[j] - m); sum += v[j]; }
#pragma unroll
    for (int o = 16; o > 0; o >>= 1)
        sum += __shfl_xor_sync(0xffffffffu, sum, o);
    const float inv = 1.f / sum;

#pragma unroll
    for (int j = 0; j < 8; j++) {
        const float p = v[j] * inv;
        const bf16 h = hi_of(p);
        const size_t o = (size_t)row * WIN + lane + 32 * j;
        sh[o] = h;
        sl[o] = lo_of(p, h);
    }
}

// ---------------- combine + split ----------------
__global__ __launch_bounds__(256) void combine_split(
    const float* __restrict__ ow, bf16* __restrict__ yh, bf16* __restrict__ yl)
{
    const int idx = blockIdx.x * 256 + threadIdx.x;
    const int c = idx & (DMODEL - 1);
    const int bt = idx >> 10;
    const int t = bt & (SEQ - 1);
    const int b = bt >> 12;

    const int w1 = t >> 7;
    float val = 0.f, cnt = 0.f;
#pragma unroll
    for (int dw = -1; dw <= 0; dw++) {
        const int w = w1 + dw;
        if (w < 0 || w >= NWIN) continue;
        const int pos = t - 128 * w;
        if (pos < 0 || pos >= WIN) continue;
        val += ow[(((size_t)(b * NWIN + w)) * WIN + pos) * DMODEL + c];
        cnt += 1.f;
    }
    const float y = val / cnt;
    const bf16 h = hi_of(y);
    yh[idx] = h;
    yl[idx] = lo_of(y, h);
}

// ---------------- launch ----------------
extern "C" void kernel_launch(void* const* d_in, const int* in_sizes, int n_in,
                              void* d_out, int out_size)
{
    const float* x  = (const float*)d_in[0];
    const float* Wq = (const float*)d_in[1];
    const float* bq = (const float*)d_in[2];
    const float* Wk = (const float*)d_in[3];
    const float* bk = (const float*)d_in[4];
    const float* Wv = (const float*)d_in[5];
    const float* bv = (const float*)d_in[6];
    const float* Wo = (const float*)d_in[7];
    const float* bo = (const float*)d_in[8];
    float* out = (float*)d_out;

    float *vb, *sb, *owb;
    cudaGetSymbolAddress((void**)&vb, g_v);
    cudaGetSymbolAddress((void**)&sb, g_s);
    cudaGetSymbolAddress((void**)&owb, g_ow);
    bf16 *xh, *xl, *qh, *ql, *kh, *kl, *vth, *vtl, *sh, *sl, *yh, *yl;
    bf16 (*wth)[DMODEL * DMODEL], (*wtl)[DMODEL * DMODEL];
    cudaGetSymbolAddress((void**)&xh, g_xh);
    cudaGetSymbolAddress((void**)&xl, g_xl);
    cudaGetSymbolAddress((void**)&qh, g_qh);
    cudaGetSymbolAddress((void**)&ql, g_ql);
    cudaGetSymbolAddress((void**)&kh, g_kh);
    cudaGetSymbolAddress((void**)&kl, g_kl);
    cudaGetSymbolAddress((void**)&vth, g_vth);
    cudaGetSymbolAddress((void**)&vtl, g_vtl);
    cudaGetSymbolAddress((void**)&sh, g_sh);
    cudaGetSymbolAddress((void**)&sl, g_sl);
    cudaGetSymbolAddress((void**)&yh, g_yh);
    cudaGetSymbolAddress((void**)&yl, g_yl);
    cudaGetSymbolAddress((void**)&wth, g_wth);
    cudaGetSymbolAddress((void**)&wtl, g_wtl);

    cudaFuncSetAttribute(gemm_qkv,
        cudaFuncAttributeMaxDynamicSharedMemorySize, GSMEM);
    cudaFuncSetAttribute(gemm_proj_f,
        cudaFuncAttributeMaxDynamicSharedMemorySize, GSMEM);
    cudaFuncSetAttribute(gemm_scores,
        cudaFuncAttributeMaxDynamicSharedMemorySize, GSMEM);
    cudaFuncSetAttribute(gemm_pv,
        cudaFuncAttributeMaxDynamicSharedMemorySize, GSMEM);

    // weight transpose+split (W[K][N] -> Wt[N][K])
    const dim3 wtg(32, 32, 1);
    split_T<<<wtg, 256>>>(Wq, wth[0], wtl[0], DMODEL, DMODEL, 0, 0);
    split_T<<<wtg, 256>>>(Wk, wth[1], wtl[1], DMODEL, DMODEL, 0, 0);
    split_T<<<wtg, 256>>>(Wv, wth[2], wtl[2], DMODEL, DMODEL, 0, 0);
    split_T<<<wtg, 256>>>(Wo, wth[3], wtl[3], DMODEL, DMODEL, 0, 0);

    split_plain<<<2048, 256>>>(x, xh, xl, MTOK * DMODEL / 4);

    // merged q/k/v projections: grid (3*8, 128)
    gemm_qkv<<<dim3(24, MTOK / 128), 256, GSMEM>>>(
        xh, xl, (const bf16*)wth, (const bf16*)wtl,
        bq, bk, bv, qh, ql, kh, kl, vb);

    split_T<<<dim3(32, SEQ / 32, BATCH), 256>>>(
        vb, vth, vtl, SEQ, DMODEL,
        (size_t)SEQ * DMODEL, (size_t)SEQ * DMODEL);

    gemm_scores<<<dim3(2, 2, NBW), 256, GSMEM>>>(qh, ql, kh, kl, sb);

    win_softmax_split<<<(NBW * WIN) / 8, 256>>>(sb, sh, sl);

    gemm_pv<<<dim3(DMODEL / 128, 2, NBW), 256, GSMEM>>>(sh, sl, vth, vtl, owb);

    combine_split<<<(MTOK * DMODEL) / 256, 256>>>(owb, yh, yl);

    gemm_proj_f<<<dim3(DMODEL / 128, MTOK / 128), 256, GSMEM>>>(
        yh, yl, wth[3], wtl[3], bo, out);
}

// round 13
// speedup vs baseline: 1.1375x; 1.0507x over previous
#include <cuda_runtime.h>
#include <cuda_bf16.h>
#include <cstdint>

// ---------------- problem constants ----------------
#define BATCH 4
#define SEQ 4096
#define DMODEL 1024
#define WIN 256
#define NWIN 31              // window starts 0,128,...,3840
#define NBW (BATCH * NWIN)   // 124
#define MTOK (BATCH * SEQ)   // 16384

typedef __nv_bfloat16 bf16;

// ---------------- scratch (static device globals, no allocs) ----------------
__device__ float g_v[(size_t)MTOK * DMODEL];
__device__ float g_s[(size_t)NBW * WIN * WIN];

__device__ bf16 g_xh[(size_t)MTOK * DMODEL];
__device__ bf16 g_xl[(size_t)MTOK * DMODEL];
__device__ bf16 g_qh[(size_t)MTOK * DMODEL];
__device__ bf16 g_ql[(size_t)MTOK * DMODEL];
__device__ bf16 g_kh[(size_t)MTOK * DMODEL];
__device__ bf16 g_kl[(size_t)MTOK * DMODEL];
__device__ bf16 g_vth[(size_t)MTOK * DMODEL];   // per-batch V^T [1024][4096]
__device__ bf16 g_vtl[(size_t)MTOK * DMODEL];
__device__ bf16 g_sh[(size_t)NBW * WIN * WIN];
__device__ bf16 g_sl[(size_t)NBW * WIN * WIN];
__device__ bf16 g_yh[(size_t)MTOK * DMODEL];
__device__ bf16 g_yl[(size_t)MTOK * DMODEL];
__device__ bf16 g_wth[4][(size_t)DMODEL * DMODEL];  // W^T splits (q,k,v,o)
__device__ bf16 g_wtl[4][(size_t)DMODEL * DMODEL];

// ---------------- primitives ----------------
__device__ __forceinline__ void mma16816(float* c, const uint32_t* a,
                                         const uint32_t* b) {
    asm volatile(
        "mma.sync.aligned.m16n8k16.row.col.f32.bf16.bf16.f32 "
        "{%0,%1,%2,%3}, {%4,%5,%6,%7}, {%8,%9}, {%0,%1,%2,%3};"
        : "+f"(c[0]), "+f"(c[1]), "+f"(c[2]), "+f"(c[3])
        : "r"(a[0]), "r"(a[1]), "r"(a[2]), "r"(a[3]), "r"(b[0]), "r"(b[1]));
}

__device__ __forceinline__ void ldsm4(uint32_t* r, uint32_t addr) {
    asm volatile(
        "ldmatrix.sync.aligned.m8n8.x4.shared.b16 {%0,%1,%2,%3}, [%4];"
        : "=r"(r[0]), "=r"(r[1]), "=r"(r[2]), "=r"(r[3])
        : "r"(addr));
}

__device__ __forceinline__ void cpa16(uint32_t s, const void* g) {
    asm volatile("cp.async.cg.shared.global [%0], [%1], 16;"
                 :: "r"(s), "l"(g) : "memory");
}
__device__ __forceinline__ void cpa_commit() {
    asm volatile("cp.async.commit_group;" ::: "memory");
}
__device__ __forceinline__ void cpa_wait1() {
    asm volatile("cp.async.wait_group 1;" ::: "memory");
}
__device__ __forceinline__ void cpa_wait0() {
    asm volatile("cp.async.wait_group 0;" ::: "memory");
}

__device__ __forceinline__ bf16 hi_of(float v) { return __float2bfloat16_rn(v); }
__device__ __forceinline__ bf16 lo_of(float v, bf16 h) {
    return __float2bfloat16_rn(v - __bfloat162float(h));
}

// ---------------- bf16x3 GEMM core (2-stage cp.async, 2 CTAs/SM) ----------
#define SROW 40
#define MATB (128 * SROW * 2)     // bytes per matrix per stage (10240)
#define STB (4 * MATB)            // bytes per stage (40960)
#define GSMEM (2 * STB)           // 81920 bytes dynamic smem -> 2 CTAs/SM

__device__ __forceinline__ void gemm_core(
    const bf16* __restrict__ Ah, const bf16* __restrict__ Al, int lda,
    const bf16* __restrict__ Bh, const bf16* __restrict__ Bl, int ldb,
    const float* __restrict__ bias, float scale,
    float* __restrict__ C, bf16* __restrict__ Ch, bf16* __restrict__ Cl,
    int ldc, int K, int by, int bx, int om)
{
    extern __shared__ __align__(16) char smbuf[];
    const uint32_t smu = (uint32_t)__cvta_generic_to_shared(smbuf);

    const int t = threadIdx.x;
    const int lane = t & 31;
    const int warp = t >> 5;
    const int wm = warp >> 1;
    const int wn = warp & 1;

    const int grow = t >> 2;
    const int gcg = (t & 3) * 8;
    const bf16* pAh = Ah + (size_t)(by + grow) * lda + gcg;
    const bf16* pAl = Al + (size_t)(by + grow) * lda + gcg;
    const bf16* pBh = Bh + (size_t)(bx + grow) * ldb + gcg;
    const bf16* pBl = Bl + (size_t)(bx + grow) * ldb + gcg;
    const size_t astep = (size_t)64 * lda;
    const size_t bstep = (size_t)64 * ldb;

    const uint32_t soffB = (uint32_t)(grow * SROW + gcg) * 2;
    const uint32_t r2 = 64 * SROW * 2;

    const int lg = lane & 7;
    const int sel = lane >> 3;
    const int radd = (sel & 1) * 8;
    const int cadd = (sel >> 1) * 8;
    const int radd_b = (sel >> 1) * 8;
    const int cadd_b = (sel & 1) * 8;

    float acc[2][8][4];
#pragma unroll
    for (int i = 0; i < 2; i++)
#pragma unroll
        for (int j = 0; j < 8; j++)
#pragma unroll
            for (int q = 0; q < 4; q++) acc[i][j][q] = 0.f;

#define ISSUE(kt, st)                                                     \
    {                                                                     \
        const size_t ko = (size_t)(kt) * 32;                              \
        const uint32_t d = smu + (st) * STB + soffB;                      \
        cpa16(d, pAh + ko);                                               \
        cpa16(d + r2, pAh + astep + ko);                                  \
        cpa16(d + MATB, pAl + ko);                                        \
        cpa16(d + MATB + r2, pAl + astep + ko);                           \
        cpa16(d + 2 * MATB, pBh + ko);                                    \
        cpa16(d + 2 * MATB + r2, pBh + bstep + ko);                       \
        cpa16(d + 3 * MATB, pBl + ko);                                    \
        cpa16(d + 3 * MATB + r2, pBl + bstep + ko);                       \
    }

    const int nt = K / 32;
    ISSUE(0, 0);
    cpa_commit();

    for (int kt = 0; kt < nt; kt++) {
        const int cur = kt & 1;
        if (kt + 1 < nt) {
            ISSUE(kt + 1, cur ^ 1);
            cpa_commit();
            cpa_wait1();
        } else {
            cpa_wait0();
        }
        __syncthreads();

        const uint32_t bAh = smu + cur * STB;
        const uint32_t bAl = bAh + MATB;
        const uint32_t bBh = bAh + 2 * MATB;
        const uint32_t bBl = bAh + 3 * MATB;

#pragma unroll
        for (int kk = 0; kk < 32; kk += 16) {
            uint32_t ah[2][4], al[2][4], bh[4][4], bl[4][4];
#pragma unroll
            for (int i = 0; i < 2; i++) {
                const uint32_t off =
                    ((wm * 32 + i * 16 + radd + lg) * SROW + kk + cadd) * 2;
                ldsm4(ah[i], bAh + off);
                ldsm4(al[i], bAl + off);
            }
#pragma unroll
            for (int jp = 0; jp < 4; jp++) {
                const uint32_t off =
                    ((wn * 64 + jp * 16 + radd_b + lg) * SROW + kk + cadd_b) * 2;
                ldsm4(bh[jp], bBh + off);
                ldsm4(bl[jp], bBl + off);
            }
#pragma unroll
            for (int i = 0; i < 2; i++)
#pragma unroll
                for (int j = 0; j < 8; j++) {
                    const uint32_t* bhp = &bh[j >> 1][(j & 1) * 2];
                    const uint32_t* blp = &bl[j >> 1][(j & 1) * 2];
                    mma16816(acc[i][j], ah[i], bhp);
                    mma16816(acc[i][j], al[i], bhp);
                    mma16816(acc[i][j], ah[i], blp);
                }
        }
        __syncthreads();
    }
#undef ISSUE

    const int lrow = lane >> 2;
    const int lcol = (lane & 3) * 2;
#pragma unroll
    for (int i = 0; i < 2; i++) {
        const int r0 = by + wm * 32 + i * 16 + lrow;
#pragma unroll
        for (int j = 0; j < 8; j++) {
            const int c = bx + wn * 64 + j * 8 + lcol;
            float b0 = 0.f, b1 = 0.f;
            if (bias) { b0 = bias[c]; b1 = bias[c + 1]; }
            const float v00 = acc[i][j][0] * scale + b0;
            const float v01 = acc[i][j][1] * scale + b1;
            const float v10 = acc[i][j][2] * scale + b0;
            const float v11 = acc[i][j][3] * scale + b1;
            if (om == 0) {
                *(float2*)&C[(size_t)r0 * ldc + c] = make_float2(v00, v01);
                *(float2*)&C[(size_t)(r0 + 8) * ldc + c] = make_float2(v10, v11);
            } else {
                const bf16 h00 = hi_of(v00), h01 = hi_of(v01);
                const bf16 h10 = hi_of(v10), h11 = hi_of(v11);
                __nv_bfloat162 hp0{h00, h01}, hp1{h10, h11};
                __nv_bfloat162 lp0{lo_of(v00, h00), lo_of(v01, h01)};
                __nv_bfloat162 lp1{lo_of(v10, h10), lo_of(v11, h11)};
                *(__nv_bfloat162*)&Ch[(size_t)r0 * ldc + c] = hp0;
                *(__nv_bfloat162*)&Ch[(size_t)(r0 + 8) * ldc + c] = hp1;
                *(__nv_bfloat162*)&Cl[(size_t)r0 * ldc + c] = lp0;
                *(__nv_bfloat162*)&Cl[(size_t)(r0 + 8) * ldc + c] = lp1;
            }
        }
    }
}

// ---------------- GEMM wrappers ----------------
// Merged Q/K/V projection: grid (24, 128). blockIdx.x>>3 selects matrix.
__global__ __launch_bounds__(256) void gemm_qkv(
    const bf16* __restrict__ xh, const bf16* __restrict__ xl,
    const bf16* __restrict__ wh, const bf16* __restrict__ wl,
    const float* __restrict__ bq, const float* __restrict__ bk,
    const float* __restrict__ bv,
    bf16* __restrict__ qh, bf16* __restrict__ ql,
    bf16* __restrict__ kh, bf16* __restrict__ kl,
    float* __restrict__ v)
{
    const int idx = blockIdx.x >> 3;          // 0=q, 1=k, 2=v
    const int bx = (blockIdx.x & 7) * 128;
    const size_t woff = (size_t)idx * DMODEL * DMODEL;
    if (idx == 0)
        gemm_core(xh, xl, DMODEL, wh + woff, wl + woff, DMODEL, bq, 1.f,
                  nullptr, qh, ql, DMODEL, DMODEL, blockIdx.y * 128, bx, 1);
    else if (idx == 1)
        gemm_core(xh, xl, DMODEL, wh + woff, wl + woff, DMODEL, bk, 1.f,
                  nullptr, kh, kl, DMODEL, DMODEL, blockIdx.y * 128, bx, 1);
    else
        gemm_core(xh, xl, DMODEL, wh + woff, wl + woff, DMODEL, bv, 1.f,
                  v, nullptr, nullptr, DMODEL, DMODEL, blockIdx.y * 128, bx, 0);
}

__global__ __launch_bounds__(256) void gemm_proj_f(
    const bf16* __restrict__ Ah, const bf16* __restrict__ Al,
    const bf16* __restrict__ Bth, const bf16* __restrict__ Btl,
    const float* __restrict__ bias, float* __restrict__ C)
{
    gemm_core(Ah, Al, DMODEL, Bth, Btl, DMODEL, bias, 1.f,
              C, nullptr, nullptr, DMODEL, DMODEL,
              blockIdx.y * 128, blockIdx.x * 128, 0);
}

__global__ __launch_bounds__(256) void gemm_scores(
    const bf16* __restrict__ qh, const bf16* __restrict__ ql,
    const bf16* __restrict__ kh, const bf16* __restrict__ kl,
    float* __restrict__ s)
{
    const int z = blockIdx.z;
    const int b = z / NWIN;
    const int w = z - b * NWIN;
    const size_t off = ((size_t)b * SEQ + 128 * w) * DMODEL;
    gemm_core(qh + off, ql + off, DMODEL, kh + off, kl + off, DMODEL,
              nullptr, 0.125f, s + (size_t)z * WIN * WIN, nullptr, nullptr,
              WIN, DMODEL, blockIdx.y * 128, blockIdx.x * 128, 0);
}

// ---------------- fused PV + window-combine ----------------
// Output token block tb (128 rows of y) = (1/cnt) * sum over contributing
// windows w of P_w[rowoff:rowoff+128, :] @ Vw^T. Writes yh/yl directly.
// Grid: (DMODEL/128, MTOK/128). blockIdx.y = tb; b = tb>>5, j = tb&31.
__global__ __launch_bounds__(256) void gemm_pv_fused(
    const bf16* __restrict__ sh, const bf16* __restrict__ sl,
    const bf16* __restrict__ vth, const bf16* __restrict__ vtl,
    bf16* __restrict__ yh, bf16* __restrict__ yl)
{
    extern __shared__ __align__(16) char smbuf[];
    const uint32_t smu = (uint32_t)__cvta_generic_to_shared(smbuf);

    const int tb = blockIdx.y;
    const int b = tb >> 5;
    const int j = tb & 31;
    const int bx = blockIdx.x * 128;
    const int by = tb * 128;              // global output row base

    // contributing windows: (j-1, rows 128..255) and (j, rows 0..127)
    int w0, ro0, w1, ro1, nseg;
    if (j == 0)       { w0 = 0;     ro0 = 0;   w1 = 0;  ro1 = 0; nseg = 1; }
    else if (j == 31) { w0 = 30;    ro0 = 128; w1 = 30; ro1 = 128; nseg = 1; }
    else              { w0 = j - 1; ro0 = 128; w1 = j;  ro1 = 0; nseg = 2; }
    const float scale = (nseg == 2) ? 0.5f : 1.f;

    const int t = threadIdx.x;
    const int lane = t & 31;
    const int warp = t >> 5;
    const int wm = warp >> 1;
    const int wn = warp & 1;

    const int grow = t >> 2;
    const int gcg = (t & 3) * 8;

    const size_t z0 = (size_t)(b * NWIN + w0) * WIN * WIN;
    const size_t z1 = (size_t)(b * NWIN + w1) * WIN * WIN;
    const bf16* pAh0 = sh + z0 + (size_t)(ro0 + grow) * WIN + gcg;
    const bf16* pAl0 = sl + z0 + (size_t)(ro0 + grow) * WIN + gcg;
    const bf16* pAh1 = sh + z1 + (size_t)(ro1 + grow) * WIN + gcg;
    const bf16* pAl1 = sl + z1 + (size_t)(ro1 + grow) * WIN + gcg;
    const size_t vbase = (size_t)b * DMODEL * SEQ + (size_t)(bx + grow) * SEQ + gcg;
    const bf16* pBh0 = vth + vbase + 128 * w0;
    const bf16* pBl0 = vtl + vbase + 128 * w0;
    const bf16* pBh1 = vth + vbase + 128 * w1;
    const bf16* pBl1 = vtl + vbase + 128 * w1;
    const size_t astep = (size_t)64 * WIN;
    const size_t bstep = (size_t)64 * SEQ;

    const uint32_t soffB = (uint32_t)(grow * SROW + gcg) * 2;
    const uint32_t r2 = 64 * SROW * 2;

    const int lg = lane & 7;
    const int sel = lane >> 3;
    const int radd = (sel & 1) * 8;
    const int cadd = (sel >> 1) * 8;
    const int radd_b = (sel >> 1) * 8;
    const int cadd_b = (sel & 1) * 8;

    float acc[2][8][4];
#pragma unroll
    for (int i = 0; i < 2; i++)
#pragma unroll
        for (int jj = 0; jj < 8; jj++)
#pragma unroll
            for (int q = 0; q < 4; q++) acc[i][jj][q] = 0.f;

#define ISSUE_F(gt, st)                                                   \
    {                                                                     \
        const int seg = (gt) >> 3;                                        \
        const size_t ko = (size_t)((gt) & 7) * 32;                        \
        const bf16* ah_ = seg ? pAh1 : pAh0;                              \
        const bf16* al_ = seg ? pAl1 : pAl0;                              \
        const bf16* bh_ = seg ? pBh1 : pBh0;                              \
        const bf16* bl_ = seg ? pBl1 : pBl0;                              \
        const uint32_t d = smu + (st) * STB + soffB;                      \
        cpa16(d, ah_ + ko);                                               \
        cpa16(d + r2, ah_ + astep + ko);                                  \
        cpa16(d + MATB, al_ + ko);                                        \
        cpa16(d + MATB + r2, al_ + astep + ko);                           \
        cpa16(d + 2 * MATB, bh_ + ko);                                    \
        cpa16(d + 2 * MATB + r2, bh_ + bstep + ko);                       \
        cpa16(d + 3 * MATB, bl_ + ko);                                    \
        cpa16(d + 3 * MATB + r2, bl_ + bstep + ko);                       \
    }

    const int nt = nseg * 8;
    ISSUE_F(0, 0);
    cpa_commit();

    for (int kt = 0; kt < nt; kt++) {
        const int cur = kt & 1;
        if (kt + 1 < nt) {
            ISSUE_F(kt + 1, cur ^ 1);
            cpa_commit();
            cpa_wait1();
        } else {
            cpa_wait0();
        }
        __syncthreads();

        const uint32_t bAh = smu + cur * STB;
        const uint32_t bAl = bAh + MATB;
        const uint32_t bBh = bAh + 2 * MATB;
        const uint32_t bBl = bAh + 3 * MATB;

#pragma unroll
        for (int kk = 0; kk < 32; kk += 16) {
            uint32_t ah[2][4], al[2][4], bh[4][4], bl[4][4];
#pragma unroll
            for (int i = 0; i < 2; i++) {
                const uint32_t off =
                    ((wm * 32 + i * 16 + radd + lg) * SROW + kk + cadd) * 2;
                ldsm4(ah[i], bAh + off);
                ldsm4(al[i], bAl + off);
            }
#pragma unroll
            for (int jp = 0; jp < 4; jp++) {
                const uint32_t off =
                    ((wn * 64 + jp * 16 + radd_b + lg) * SROW + kk + cadd_b) * 2;
                ldsm4(bh[jp], bBh + off);
                ldsm4(bl[jp], bBl + off);
            }
#pragma unroll
            for (int i = 0; i < 2; i++)
#pragma unroll
                for (int jj = 0; jj < 8; jj++) {
                    const uint32_t* bhp = &bh[jj >> 1][(jj & 1) * 2];
                    const uint32_t* blp = &bl[jj >> 1][(jj & 1) * 2];
                    mma16816(acc[i][jj], ah[i], bhp);
                    mma16816(acc[i][jj], al[i], bhp);
                    mma16816(acc[i][jj], ah[i], blp);
                }
        }
        __syncthreads();
    }
#undef ISSUE_F

    const int lrow = lane >> 2;
    const int lcol = (lane & 3) * 2;
#pragma unroll
    for (int i = 0; i < 2; i++) {
        const int r0 = by + wm * 32 + i * 16 + lrow;
#pragma unroll
        for (int jj = 0; jj < 8; jj++) {
            const int c = bx + wn * 64 + jj * 8 + lcol;
            const float v00 = acc[i][jj][0] * scale;
            const float v01 = acc[i][jj][1] * scale;
            const float v10 = acc[i][jj][2] * scale;
            const float v11 = acc[i][jj][3] * scale;
            const bf16 h00 = hi_of(v00), h01 = hi_of(v01);
            const bf16 h10 = hi_of(v10), h11 = hi_of(v11);
            __nv_bfloat162 hp0{h00, h01}, hp1{h10, h11};
            __nv_bfloat162 lp0{lo_of(v00, h00), lo_of(v01, h01)};
            __nv_bfloat162 lp1{lo_of(v10, h10), lo_of(v11, h11)};
            *(__nv_bfloat162*)&yh[(size_t)r0 * DMODEL + c] = hp0;
            *(__nv_bfloat162*)&yh[(size_t)(r0 + 8) * DMODEL + c] = hp1;
            *(__nv_bfloat162*)&yl[(size_t)r0 * DMODEL + c] = lp0;
            *(__nv_bfloat162*)&yl[(size_t)(r0 + 8) * DMODEL + c] = lp1;
        }
    }
}

// ---------------- split kernels ----------------
__global__ __launch_bounds__(256) void split_plain(
    const float* __restrict__ src, bf16* __restrict__ h,
    bf16* __restrict__ l, int n4)
{
    for (int i = blockIdx.x * 256 + threadIdx.x; i < n4;
         i += gridDim.x * 256) {
        float4 v = ((const float4*)src)[i];
        bf16 hx = hi_of(v.x), hy = hi_of(v.y), hz = hi_of(v.z), hw = hi_of(v.w);
        __nv_bfloat162 h01{hx, hy}, h23{hz, hw};
        __nv_bfloat162 l01{lo_of(v.x, hx), lo_of(v.y, hy)};
        __nv_bfloat162 l23{lo_of(v.z, hz), lo_of(v.w, hw)};
        ((__nv_bfloat162*)h)[2 * i]     = h01;
        ((__nv_bfloat162*)h)[2 * i + 1] = h23;
        ((__nv_bfloat162*)l)[2 * i]     = l01;
        ((__nv_bfloat162*)l)[2 * i + 1] = l23;
    }
}

// transpose + split: src [R][Cc] fp32 -> dst [Cc][R] bf16 hi/lo
__global__ __launch_bounds__(256) void split_T(
    const float* __restrict__ src, bf16* __restrict__ dh,
    bf16* __restrict__ dl, int R, int Cc, size_t sStride, size_t dStride)
{
    __shared__ float tile[32][33];
    const float* S = src + blockIdx.z * sStride;
    bf16* H = dh + blockIdx.z * dStride;
    bf16* L = dl + blockIdx.z * dStride;

    const int c0 = blockIdx.x * 32;
    const int r0 = blockIdx.y * 32;
    const int tx = threadIdx.x & 31;
    const int ty = threadIdx.x >> 5;

#pragma unroll
    for (int k = 0; k < 4; k++)
        tile[ty + 8 * k][tx] = S[(size_t)(r0 + ty + 8 * k) * Cc + c0 + tx];
    __syncthreads();

#pragma unroll
    for (int k = 0; k < 4; k++) {
        const float v = tile[tx][ty + 8 * k];
        const bf16 hv = hi_of(v);
        const bf16 lv = lo_of(v, hv);
        const size_t o = (size_t)(c0 + ty + 8 * k) * R + r0 + tx;
        H[o] = hv;
        L[o] = lv;
    }
}

// ---------------- softmax + split (warp per 256-wide row) ----------------
__global__ __launch_bounds__(256) void win_softmax_split(
    const float* __restrict__ s, bf16* __restrict__ sh, bf16* __restrict__ sl)
{
    const int row = blockIdx.x * 8 + (threadIdx.x >> 5);
    const int lane = threadIdx.x & 31;
    const float* r = s + (size_t)row * WIN;

    float v[8];
    float m = -1e30f;
#pragma unroll
    for (int j = 0; j < 8; j++) {
        v[j] = r[lane + 32 * j];
        m = fmaxf(m, v[j]);
    }
#pragma unroll
    for (int o = 16; o > 0; o >>= 1)
        m = fmaxf(m, __shfl_xor_sync(0xffffffffu, m, o));

    float sum = 0.f;
#pragma unroll
    for (int j = 0; j < 8; j++) { v[j] = expf(v[j] - m); sum += v[j]; }
#pragma unroll
    for (int o = 16; o > 0; o >>= 1)
        sum += __shfl_xor_sync(0xffffffffu, sum, o);
    const float inv = 1.f / sum;

#pragma unroll
    for (int j = 0; j < 8; j++) {
        const float p = v[j] * inv;
        const bf16 h = hi_of(p);
        const size_t o = (size_t)row * WIN + lane + 32 * j;
        sh[o] = h;
        sl[o] = lo_of(p, h);
    }
}

// ---------------- launch ----------------
extern "C" void kernel_launch(void* const* d_in, const int* in_sizes, int n_in,
                              void* d_out, int out_size)
{
    const float* x  = (const float*)d_in[0];
    const float* Wq = (const float*)d_in[1];
    const float* bq = (const float*)d_in[2];
    const float* Wk = (const float*)d_in[3];
    const float* bk = (const float*)d_in[4];
    const float* Wv = (const float*)d_in[5];
    const float* bv = (const float*)d_in[6];
    const float* Wo = (const float*)d_in[7];
    const float* bo = (const float*)d_in[8];
    float* out = (float*)d_out;

    float *vb, *sb;
    cudaGetSymbolAddress((void**)&vb, g_v);
    cudaGetSymbolAddress((void**)&sb, g_s);
    bf16 *xh, *xl, *qh, *ql, *kh, *kl, *vth, *vtl, *sh, *sl, *yh, *yl;
    bf16 (*wth)[DMODEL * DMODEL], (*wtl)[DMODEL * DMODEL];
    cudaGetSymbolAddress((void**)&xh, g_xh);
    cudaGetSymbolAddress((void**)&xl, g_xl);
    cudaGetSymbolAddress((void**)&qh, g_qh);
    cudaGetSymbolAddress((void**)&ql, g_ql);
    cudaGetSymbolAddress((void**)&kh, g_kh);
    cudaGetSymbolAddress((void**)&kl, g_kl);
    cudaGetSymbolAddress((void**)&vth, g_vth);
    cudaGetSymbolAddress((void**)&vtl, g_vtl);
    cudaGetSymbolAddress((void**)&sh, g_sh);
    cudaGetSymbolAddress((void**)&sl, g_sl);
    cudaGetSymbolAddress((void**)&yh, g_yh);
    cudaGetSymbolAddress((void**)&yl, g_yl);
    cudaGetSymbolAddress((void**)&wth, g_wth);
    cudaGetSymbolAddress((void**)&wtl, g_wtl);

    cudaFuncSetAttribute(gemm_qkv,
        cudaFuncAttributeMaxDynamicSharedMemorySize, GSMEM);
    cudaFuncSetAttribute(gemm_proj_f,
        cudaFuncAttributeMaxDynamicSharedMemorySize, GSMEM);
    cudaFuncSetAttribute(gemm_scores,
        cudaFuncAttributeMaxDynamicSharedMemorySize, GSMEM);
    cudaFuncSetAttribute(gemm_pv_fused,
        cudaFuncAttributeMaxDynamicSharedMemorySize, GSMEM);

    // weight transpose+split (W[K][N] -> Wt[N][K])
    const dim3 wtg(32, 32, 1);
    split_T<<<wtg, 256>>>(Wq, wth[0], wtl[0], DMODEL, DMODEL, 0, 0);
    split_T<<<wtg, 256>>>(Wk, wth[1], wtl[1], DMODEL, DMODEL, 0, 0);
    split_T<<<wtg, 256>>>(Wv, wth[2], wtl[2], DMODEL, DMODEL, 0, 0);
    split_T<<<wtg, 256>>>(Wo, wth[3], wtl[3], DMODEL, DMODEL, 0, 0);

    split_plain<<<2048, 256>>>(x, xh, xl, MTOK * DMODEL / 4);

    // merged q/k/v projections: grid (3*8, 128)
    gemm_qkv<<<dim3(24, MTOK / 128), 256, GSMEM>>>(
        xh, xl, (const bf16*)wth, (const bf16*)wtl,
        bq, bk, bv, qh, ql, kh, kl, vb);

    split_T<<<dim3(32, SEQ / 32, BATCH), 256>>>(
        vb, vth, vtl, SEQ, DMODEL,
        (size_t)SEQ * DMODEL, (size_t)SEQ * DMODEL);

    gemm_scores<<<dim3(2, 2, NBW), 256, GSMEM>>>(qh, ql, kh, kl, sb);

    win_softmax_split<<<(NBW * WIN) / 8, 256>>>(sb, sh, sl);

    // fused PV + window combine: writes yh/yl directly
    gemm_pv_fused<<<dim3(DMODEL / 128, MTOK / 128), 256, GSMEM>>>(
        sh, sl, vth, vtl, yh, yl);

    gemm_proj_f<<<dim3(DMODEL / 128, MTOK / 128), 256, GSMEM>>>(
        yh, yl, wth[3], wtl[3], bo, out);
}

// round 14
// speedup vs baseline: 1.2369x; 1.0874x over previous
#include <cuda_runtime.h>
#include <cuda_bf16.h>
#include <cstdint>

// ---------------- problem constants ----------------
#define BATCH 4
#define SEQ 4096
#define DMODEL 1024
#define WIN 256
#define NWIN 31              // window starts 0,128,...,3840
#define NBW (BATCH * NWIN)   // 124
#define MTOK (BATCH * SEQ)   // 16384
#define NQB 32               // 128-row query blocks per sequence

typedef __nv_bfloat16 bf16;

// ---------------- scratch (static device globals, no allocs) ----------------
__device__ float g_v[(size_t)MTOK * DMODEL];
// block-tridiagonal scores: [b][i][slot(d+1)] 128x128 fp32, slot d = j-i in {-1,0,1}
__device__ float g_sblk[(size_t)BATCH * NQB * 3 * 128 * 128];

__device__ bf16 g_xh[(size_t)MTOK * DMODEL];
__device__ bf16 g_xl[(size_t)MTOK * DMODEL];
__device__ bf16 g_qh[(size_t)MTOK * DMODEL];
__device__ bf16 g_ql[(size_t)MTOK * DMODEL];
__device__ bf16 g_kh[(size_t)MTOK * DMODEL];
__device__ bf16 g_kl[(size_t)MTOK * DMODEL];
__device__ bf16 g_vth[(size_t)MTOK * DMODEL];   // per-batch V^T [1024][4096]
__device__ bf16 g_vtl[(size_t)MTOK * DMODEL];
__device__ bf16 g_sh[(size_t)NBW * WIN * WIN];
__device__ bf16 g_sl[(size_t)NBW * WIN * WIN];
__device__ bf16 g_yh[(size_t)MTOK * DMODEL];
__device__ bf16 g_yl[(size_t)MTOK * DMODEL];
__device__ bf16 g_wth[4][(size_t)DMODEL * DMODEL];  // W^T splits (q,k,v,o)
__device__ bf16 g_wtl[4][(size_t)DMODEL * DMODEL];

// ---------------- primitives ----------------
__device__ __forceinline__ void mma16816(float* c, const uint32_t* a,
                                         const uint32_t* b) {
    asm volatile(
        "mma.sync.aligned.m16n8k16.row.col.f32.bf16.bf16.f32 "
        "{%0,%1,%2,%3}, {%4,%5,%6,%7}, {%8,%9}, {%0,%1,%2,%3};"
        : "+f"(c[0]), "+f"(c[1]), "+f"(c[2]), "+f"(c[3])
        : "r"(a[0]), "r"(a[1]), "r"(a[2]), "r"(a[3]), "r"(b[0]), "r"(b[1]));
}

__device__ __forceinline__ void ldsm4(uint32_t* r, uint32_t addr) {
    asm volatile(
        "ldmatrix.sync.aligned.m8n8.x4.shared.b16 {%0,%1,%2,%3}, [%4];"
        : "=r"(r[0]), "=r"(r[1]), "=r"(r[2]), "=r"(r[3])
        : "r"(addr));
}

__device__ __forceinline__ void cpa16(uint32_t s, const void* g) {
    asm volatile("cp.async.cg.shared.global [%0], [%1], 16;"
                 :: "r"(s), "l"(g) : "memory");
}
__device__ __forceinline__ void cpa_commit() {
    asm volatile("cp.async.commit_group;" ::: "memory");
}
__device__ __forceinline__ void cpa_wait0() {
    asm volatile("cp.async.wait_group 0;" ::: "memory");
}

__device__ __forceinline__ bf16 hi_of(float v) { return __float2bfloat16_rn(v); }
__device__ __forceinline__ bf16 lo_of(float v, bf16 h) {
    return __float2bfloat16_rn(v - __bfloat162float(h));
}

// ---------------- bf16x3 GEMM core (2-stage cp.async, 1 sync/tile) --------
#define SROW 40
#define MATB (128 * SROW * 2)     // bytes per matrix per stage (10240)
#define STB (4 * MATB)            // bytes per stage (40960)
#define GSMEM (2 * STB)           // 81920 bytes dynamic smem -> 2 CTAs/SM

__device__ __forceinline__ void gemm_core(
    const bf16* __restrict__ Ah, const bf16* __restrict__ Al, int lda,
    const bf16* __restrict__ Bh, const bf16* __restrict__ Bl, int ldb,
    const float* __restrict__ bias, float scale,
    float* __restrict__ C, bf16* __restrict__ Ch, bf16* __restrict__ Cl,
    int ldc, int K, int by, int bx, int om)
{
    extern __shared__ __align__(16) char smbuf[];
    const uint32_t smu = (uint32_t)__cvta_generic_to_shared(smbuf);

    const int t = threadIdx.x;
    const int lane = t & 31;
    const int warp = t >> 5;
    const int wm = warp >> 1;
    const int wn = warp & 1;

    const int grow = t >> 2;
    const int gcg = (t & 3) * 8;
    const bf16* pAh = Ah + (size_t)(by + grow) * lda + gcg;
    const bf16* pAl = Al + (size_t)(by + grow) * lda + gcg;
    const bf16* pBh = Bh + (size_t)(bx + grow) * ldb + gcg;
    const bf16* pBl = Bl + (size_t)(bx + grow) * ldb + gcg;
    const size_t astep = (size_t)64 * lda;
    const size_t bstep = (size_t)64 * ldb;

    const uint32_t soffB = (uint32_t)(grow * SROW + gcg) * 2;
    const uint32_t r2 = 64 * SROW * 2;

    const int lg = lane & 7;
    const int sel = lane >> 3;
    const int radd = (sel & 1) * 8;
    const int cadd = (sel >> 1) * 8;
    const int radd_b = (sel >> 1) * 8;
    const int cadd_b = (sel & 1) * 8;

    float acc[2][8][4];
#pragma unroll
    for (int i = 0; i < 2; i++)
#pragma unroll
        for (int j = 0; j < 8; j++)
#pragma unroll
            for (int q = 0; q < 4; q++) acc[i][j][q] = 0.f;

#define ISSUE(kt, st)                                                     \
    {                                                                     \
        const size_t ko = (size_t)(kt) * 32;                              \
        const uint32_t d = smu + (st) * STB + soffB;                      \
        cpa16(d, pAh + ko);                                               \
        cpa16(d + r2, pAh + astep + ko);                                  \
        cpa16(d + MATB, pAl + ko);                                        \
        cpa16(d + MATB + r2, pAl + astep + ko);                           \
        cpa16(d + 2 * MATB, pBh + ko);                                    \
        cpa16(d + 2 * MATB + r2, pBh + bstep + ko);                       \
        cpa16(d + 3 * MATB, pBl + ko);                                    \
        cpa16(d + 3 * MATB + r2, pBl + bstep + ko);                       \
        cpa_commit();                                                     \
    }

    const int nt = K / 32;
    ISSUE(0, 0);

    for (int kt = 0; kt < nt; kt++) {
        const int cur = kt & 1;
        cpa_wait0();
        __syncthreads();
        // all warps done reading stage cur^1 (compute kt-1) -> safe to refill
        if (kt + 1 < nt) ISSUE(kt + 1, cur ^ 1);

        const uint32_t bAh = smu + cur * STB;
        const uint32_t bAl = bAh + MATB;
        const uint32_t bBh = bAh + 2 * MATB;
        const uint32_t bBl = bAh + 3 * MATB;

#pragma unroll
        for (int kk = 0; kk < 32; kk += 16) {
            uint32_t ah[2][4], al[2][4], bh[4][4], bl[4][4];
#pragma unroll
            for (int i = 0; i < 2; i++) {
                const uint32_t off =
                    ((wm * 32 + i * 16 + radd + lg) * SROW + kk + cadd) * 2;
                ldsm4(ah[i], bAh + off);
                ldsm4(al[i], bAl + off);
            }
#pragma unroll
            for (int jp = 0; jp < 4; jp++) {
                const uint32_t off =
                    ((wn * 64 + jp * 16 + radd_b + lg) * SROW + kk + cadd_b) * 2;
                ldsm4(bh[jp], bBh + off);
                ldsm4(bl[jp], bBl + off);
            }
#pragma unroll
            for (int i = 0; i < 2; i++)
#pragma unroll
                for (int j = 0; j < 8; j++) {
                    const uint32_t* bhp = &bh[j >> 1][(j & 1) * 2];
                    const uint32_t* blp = &bl[j >> 1][(j & 1) * 2];
                    mma16816(acc[i][j], ah[i], bhp);
                    mma16816(acc[i][j], al[i], bhp);
                    mma16816(acc[i][j], ah[i], blp);
                }
        }
    }
#undef ISSUE

    const int lrow = lane >> 2;
    const int lcol = (lane & 3) * 2;
#pragma unroll
    for (int i = 0; i < 2; i++) {
        const int r0 = by + wm * 32 + i * 16 + lrow;
#pragma unroll
        for (int j = 0; j < 8; j++) {
            const int c = bx + wn * 64 + j * 8 + lcol;
            float b0 = 0.f, b1 = 0.f;
            if (bias) { b0 = bias[c]; b1 = bias[c + 1]; }
            const float v00 = acc[i][j][0] * scale + b0;
            const float v01 = acc[i][j][1] * scale + b1;
            const float v10 = acc[i][j][2] * scale + b0;
            const float v11 = acc[i][j][3] * scale + b1;
            if (om == 0) {
                *(float2*)&C[(size_t)r0 * ldc + c] = make_float2(v00, v01);
                *(float2*)&C[(size_t)(r0 + 8) * ldc + c] = make_float2(v10, v11);
            } else {
                const bf16 h00 = hi_of(v00), h01 = hi_of(v01);
                const bf16 h10 = hi_of(v10), h11 = hi_of(v11);
                __nv_bfloat162 hp0{h00, h01}, hp1{h10, h11};
                __nv_bfloat162 lp0{lo_of(v00, h00), lo_of(v01, h01)};
                __nv_bfloat162 lp1{lo_of(v10, h10), lo_of(v11, h11)};
                *(__nv_bfloat162*)&Ch[(size_t)r0 * ldc + c] = hp0;
                *(__nv_bfloat162*)&Ch[(size_t)(r0 + 8) * ldc + c] = hp1;
                *(__nv_bfloat162*)&Cl[(size_t)r0 * ldc + c] = lp0;
                *(__nv_bfloat162*)&Cl[(size_t)(r0 + 8) * ldc + c] = lp1;
            }
        }
    }
}

// ---------------- GEMM wrappers ----------------
// Merged Q/K/V projection: grid (24, 128). blockIdx.x>>3 selects matrix.
__global__ __launch_bounds__(256) void gemm_qkv(
    const bf16* __restrict__ xh, const bf16* __restrict__ xl,
    const bf16* __restrict__ wh, const bf16* __restrict__ wl,
    const float* __restrict__ bq, const float* __restrict__ bk,
    const float* __restrict__ bv,
    bf16* __restrict__ qh, bf16* __restrict__ ql,
    bf16* __restrict__ kh, bf16* __restrict__ kl,
    float* __restrict__ v)
{
    const int idx = blockIdx.x >> 3;          // 0=q, 1=k, 2=v
    const int bx = (blockIdx.x & 7) * 128;
    const size_t woff = (size_t)idx * DMODEL * DMODEL;
    if (idx == 0)
        gemm_core(xh, xl, DMODEL, wh + woff, wl + woff, DMODEL, bq, 1.f,
                  nullptr, qh, ql, DMODEL, DMODEL, blockIdx.y * 128, bx, 1);
    else if (idx == 1)
        gemm_core(xh, xl, DMODEL, wh + woff, wl + woff, DMODEL, bk, 1.f,
                  nullptr, kh, kl, DMODEL, DMODEL, blockIdx.y * 128, bx, 1);
    else
        gemm_core(xh, xl, DMODEL, wh + woff, wl + woff, DMODEL, bv, 1.f,
                  v, nullptr, nullptr, DMODEL, DMODEL, blockIdx.y * 128, bx, 0);
}

__global__ __launch_bounds__(256) void gemm_proj_f(
    const bf16* __restrict__ Ah, const bf16* __restrict__ Al,
    const bf16* __restrict__ Bth, const bf16* __restrict__ Btl,
    const float* __restrict__ bias, float* __restrict__ C)
{
    gemm_core(Ah, Al, DMODEL, Bth, Btl, DMODEL, bias, 1.f,
              C, nullptr, nullptr, DMODEL, DMODEL,
              blockIdx.y * 128, blockIdx.x * 128, 0);
}

// Unique score blocks: S_blk(b,i,slot) = 0.125 * Qblk(i) @ Kblk(i+slot-1)^T
// grid (3, 1, BATCH*NQB). Invalid corner slots skipped.
__global__ __launch_bounds__(256) void gemm_scores_blk(
    const bf16* __restrict__ qh, const bf16* __restrict__ ql,
    const bf16* __restrict__ kh, const bf16* __restrict__ kl,
    float* __restrict__ sblk)
{
    const int z = blockIdx.z;          // b*NQB + i
    const int b = z >> 5;
    const int i = z & (NQB - 1);
    const int s = blockIdx.x;          // slot 0..2, j = i + s - 1
    const int j = i + s - 1;
    if (j < 0 || j >= NQB) return;
    const size_t qoff = ((size_t)b * SEQ + (size_t)i * 128) * DMODEL;
    const size_t koff = ((size_t)b * SEQ + (size_t)j * 128) * DMODEL;
    gemm_core(qh + qoff, ql + qoff, DMODEL, kh + koff, kl + koff, DMODEL,
              nullptr, 0.125f,
              sblk + ((size_t)z * 3 + s) * (128 * 128), nullptr, nullptr,
              128, DMODEL, 0, 0, 0);
}

// ---------------- fused PV + window-combine ----------------
__global__ __launch_bounds__(256) void gemm_pv_fused(
    const bf16* __restrict__ sh, const bf16* __restrict__ sl,
    const bf16* __restrict__ vth, const bf16* __restrict__ vtl,
    bf16* __restrict__ yh, bf16* __restrict__ yl)
{
    extern __shared__ __align__(16) char smbuf[];
    const uint32_t smu = (uint32_t)__cvta_generic_to_shared(smbuf);

    const int tb = blockIdx.y;
    const int b = tb >> 5;
    const int j = tb & 31;
    const int bx = blockIdx.x * 128;
    const int by = tb * 128;

    int w0, ro0, w1, ro1, nseg;
    if (j == 0)       { w0 = 0;     ro0 = 0;   w1 = 0;  ro1 = 0; nseg = 1; }
    else if (j == 31) { w0 = 30;    ro0 = 128; w1 = 30; ro1 = 128; nseg = 1; }
    else              { w0 = j - 1; ro0 = 128; w1 = j;  ro1 = 0; nseg = 2; }
    const float scale = (nseg == 2) ? 0.5f : 1.f;

    const int t = threadIdx.x;
    const int lane = t & 31;
    const int warp = t >> 5;
    const int wm = warp >> 1;
    const int wn = warp & 1;

    const int grow = t >> 2;
    const int gcg = (t & 3) * 8;

    const size_t z0 = (size_t)(b * NWIN + w0) * WIN * WIN;
    const size_t z1 = (size_t)(b * NWIN + w1) * WIN * WIN;
    const bf16* pAh0 = sh + z0 + (size_t)(ro0 + grow) * WIN + gcg;
    const bf16* pAl0 = sl + z0 + (size_t)(ro0 + grow) * WIN + gcg;
    const bf16* pAh1 = sh + z1 + (size_t)(ro1 + grow) * WIN + gcg;
    const bf16* pAl1 = sl + z1 + (size_t)(ro1 + grow) * WIN + gcg;
    const size_t vbase = (size_t)b * DMODEL * SEQ + (size_t)(bx + grow) * SEQ + gcg;
    const bf16* pBh0 = vth + vbase + 128 * w0;
    const bf16* pBl0 = vtl + vbase + 128 * w0;
    const bf16* pBh1 = vth + vbase + 128 * w1;
    const bf16* pBl1 = vtl + vbase + 128 * w1;
    const size_t astep = (size_t)64 * WIN;
    const size_t bstep = (size_t)64 * SEQ;

    const uint32_t soffB = (uint32_t)(grow * SROW + gcg) * 2;
    const uint32_t r2 = 64 * SROW * 2;

    const int lg = lane & 7;
    const int sel = lane >> 3;
    const int radd = (sel & 1) * 8;
    const int cadd = (sel >> 1) * 8;
    const int radd_b = (sel >> 1) * 8;
    const int cadd_b = (sel & 1) * 8;

    float acc[2][8][4];
#pragma unroll
    for (int i = 0; i < 2; i++)
#pragma unroll
        for (int jj = 0; jj < 8; jj++)
#pragma unroll
            for (int q = 0; q < 4; q++) acc[i][jj][q] = 0.f;

#define ISSUE_F(gt, st)                                                   \
    {                                                                     \
        const int seg = (gt) >> 3;                                        \
        const size_t ko = (size_t)((gt) & 7) * 32;                        \
        const bf16* ah_ = seg ? pAh1 : pAh0;                              \
        const bf16* al_ = seg ? pAl1 : pAl0;                              \
        const bf16* bh_ = seg ? pBh1 : pBh0;                              \
        const bf16* bl_ = seg ? pBl1 : pBl0;                              \
        const uint32_t d = smu + (st) * STB + soffB;                      \
        cpa16(d, ah_ + ko);                                               \
        cpa16(d + r2, ah_ + astep + ko);                                  \
        cpa16(d + MATB, al_ + ko);                                        \
        cpa16(d + MATB + r2, al_ + astep + ko);                           \
        cpa16(d + 2 * MATB, bh_ + ko);                                    \
        cpa16(d + 2 * MATB + r2, bh_ + bstep + ko);                       \
        cpa16(d + 3 * MATB, bl_ + ko);                                    \
        cpa16(d + 3 * MATB + r2, bl_ + bstep + ko);                       \
        cpa_commit();                                                     \
    }

    const int nt = nseg * 8;
    ISSUE_F(0, 0);

    for (int kt = 0; kt < nt; kt++) {
        const int cur = kt & 1;
        cpa_wait0();
        __syncthreads();
        if (kt + 1 < nt) ISSUE_F(kt + 1, cur ^ 1);

        const uint32_t bAh = smu + cur * STB;
        const uint32_t bAl = bAh + MATB;
        const uint32_t bBh = bAh + 2 * MATB;
        const uint32_t bBl = bAh + 3 * MATB;

#pragma unroll
        for (int kk = 0; kk < 32; kk += 16) {
            uint32_t ah[2][4], al[2][4], bh[4][4], bl[4][4];
#pragma unroll
            for (int i = 0; i < 2; i++) {
                const uint32_t off =
                    ((wm * 32 + i * 16 + radd + lg) * SROW + kk + cadd) * 2;
                ldsm4(ah[i], bAh + off);
                ldsm4(al[i], bAl + off);
            }
#pragma unroll
            for (int jp = 0; jp < 4; jp++) {
                const uint32_t off =
                    ((wn * 64 + jp * 16 + radd_b + lg) * SROW + kk + cadd_b) * 2;
                ldsm4(bh[jp], bBh + off);
                ldsm4(bl[jp], bBl + off);
            }
#pragma unroll
            for (int i = 0; i < 2; i++)
#pragma unroll
                for (int jj = 0; jj < 8; jj++) {
                    const uint32_t* bhp = &bh[jj >> 1][(jj & 1) * 2];
                    const uint32_t* blp = &bl[jj >> 1][(jj & 1) * 2];
                    mma16816(acc[i][jj], ah[i], bhp);
                    mma16816(acc[i][jj], al[i], bhp);
                    mma16816(acc[i][jj], ah[i], blp);
                }
        }
    }
#undef ISSUE_F

    const int lrow = lane >> 2;
    const int lcol = (lane & 3) * 2;
#pragma unroll
    for (int i = 0; i < 2; i++) {
        const int r0 = by + wm * 32 + i * 16 + lrow;
#pragma unroll
        for (int jj = 0; jj < 8; jj++) {
            const int c = bx + wn * 64 + jj * 8 + lcol;
            const float v00 = acc[i][jj][0] * scale;
            const float v01 = acc[i][jj][1] * scale;
            const float v10 = acc[i][jj][2] * scale;
            const float v11 = acc[i][jj][3] * scale;
            const bf16 h00 = hi_of(v00), h01 = hi_of(v01);
            const bf16 h10 = hi_of(v10), h11 = hi_of(v11);
            __nv_bfloat162 hp0{h00, h01}, hp1{h10, h11};
            __nv_bfloat162 lp0{lo_of(v00, h00), lo_of(v01, h01)};
            __nv_bfloat162 lp1{lo_of(v10, h10), lo_of(v11, h11)};
            *(__nv_bfloat162*)&yh[(size_t)r0 * DMODEL + c] = hp0;
            *(__nv_bfloat162*)&yh[(size_t)(r0 + 8) * DMODEL + c] = hp1;
            *(__nv_bfloat162*)&yl[(size_t)r0 * DMODEL + c] = lp0;
            *(__nv_bfloat162*)&yl[(size_t)(r0 + 8) * DMODEL + c] = lp1;
        }
    }
}

// ---------------- split kernels ----------------
__global__ __launch_bounds__(256) void split_plain(
    const float* __restrict__ src, bf16* __restrict__ h,
    bf16* __restrict__ l, int n4)
{
    for (int i = blockIdx.x * 256 + threadIdx.x; i < n4;
         i += gridDim.x * 256) {
        float4 v = ((const float4*)src)[i];
        bf16 hx = hi_of(v.x), hy = hi_of(v.y), hz = hi_of(v.z), hw = hi_of(v.w);
        __nv_bfloat162 h01{hx, hy}, h23{hz, hw};
        __nv_bfloat162 l01{lo_of(v.x, hx), lo_of(v.y, hy)};
        __nv_bfloat162 l23{lo_of(v.z, hz), lo_of(v.w, hw)};
        ((__nv_bfloat162*)h)[2 * i]     = h01;
        ((__nv_bfloat162*)h)[2 * i + 1] = h23;
        ((__nv_bfloat162*)l)[2 * i]     = l01;
        ((__nv_bfloat162*)l)[2 * i + 1] = l23;
    }
}

// transpose + split: src [R][Cc] fp32 -> dst [Cc][R] bf16 hi/lo
__global__ __launch_bounds__(256) void split_T(
    const float* __restrict__ src, bf16* __restrict__ dh,
    bf16* __restrict__ dl, int R, int Cc, size_t sStride, size_t dStride)
{
    __shared__ float tile[32][33];
    const float* S = src + blockIdx.z * sStride;
    bf16* H = dh + blockIdx.z * dStride;
    bf16* L = dl + blockIdx.z * dStride;

    const int c0 = blockIdx.x * 32;
    const int r0 = blockIdx.y * 32;
    const int tx = threadIdx.x & 31;
    const int ty = threadIdx.x >> 5;

#pragma unroll
    for (int k = 0; k < 4; k++)
        tile[ty + 8 * k][tx] = S[(size_t)(r0 + ty + 8 * k) * Cc + c0 + tx];
    __syncthreads();

#pragma unroll
    for (int k = 0; k < 4; k++) {
        const float v = tile[tx][ty + 8 * k];
        const bf16 hv = hi_of(v);
        const bf16 lv = lo_of(v, hv);
        const size_t o = (size_t)(c0 + ty + 8 * k) * R + r0 + tx;
        H[o] = hv;
        L[o] = lv;
    }
}

// ---------------- softmax + split, gathering from block-tridiagonal S -----
// warp per window-row; window w row r: query block i = w + (r>=128),
// left keys = block (i, slot top?1:0), right keys = block (i, slot top?2:1).
__global__ __launch_bounds__(256) void win_softmax_split(
    const float* __restrict__ sblk, bf16* __restrict__ sh, bf16* __restrict__ sl)
{
    const int gw = blockIdx.x * 8 + (threadIdx.x >> 5);   // 0..NBW*WIN-1
    const int lane = threadIdx.x & 31;
    const int r = gw & (WIN - 1);
    const int zw = gw >> 8;                                // b*NWIN + w
    const int b = zw / NWIN;
    const int w = zw - b * NWIN;
    const int top = (r < 128) ? 1 : 0;
    const int i = w + 1 - top;
    const int rloc = r & 127;
    const int sL = top ? 1 : 0;
    const int sR = top ? 2 : 1;

    const size_t blkbase = (size_t)(b * NQB + i) * 3 * (128 * 128)
                           + (size_t)rloc * 128;
    const float* L = sblk + blkbase + (size_t)sL * (128 * 128);
    const float* R = sblk + blkbase + (size_t)sR * (128 * 128);

    float v[8];
    float m = -1e30f;
#pragma unroll
    for (int k = 0; k < 4; k++) {
        v[k] = L[lane + 32 * k];
        v[4 + k] = R[lane + 32 * k];
    }
#pragma unroll
    for (int k = 0; k < 8; k++) m = fmaxf(m, v[k]);
#pragma unroll
    for (int o = 16; o > 0; o >>= 1)
        m = fmaxf(m, __shfl_xor_sync(0xffffffffu, m, o));

    float sum = 0.f;
#pragma unroll
    for (int k = 0; k < 8; k++) { v[k] = expf(v[k] - m); sum += v[k]; }
#pragma unroll
    for (int o = 16; o > 0; o >>= 1)
        sum += __shfl_xor_sync(0xffffffffu, sum, o);
    const float inv = 1.f / sum;

    const size_t rowb = (size_t)zw * WIN * WIN + (size_t)r * WIN;
#pragma unroll
    for (int k = 0; k < 8; k++) {
        const float p = v[k] * inv;
        const bf16 h = hi_of(p);
        const int col = (k < 4) ? (lane + 32 * k) : (128 + lane + 32 * (k - 4));
        sh[rowb + col] = h;
        sl[rowb + col] = lo_of(p, h);
    }
}

// ---------------- launch ----------------
extern "C" void kernel_launch(void* const* d_in, const int* in_sizes, int n_in,
                              void* d_out, int out_size)
{
    const float* x  = (const float*)d_in[0];
    const float* Wq = (const float*)d_in[1];
    const float* bq = (const float*)d_in[2];
    const float* Wk = (const float*)d_in[3];
    const float* bk = (const float*)d_in[4];
    const float* Wv = (const float*)d_in[5];
    const float* bv = (const float*)d_in[6];
    const float* Wo = (const float*)d_in[7];
    const float* bo = (const float*)d_in[8];
    float* out = (float*)d_out;

    float *vb, *sblk;
    cudaGetSymbolAddress((void**)&vb, g_v);
    cudaGetSymbolAddress((void**)&sblk, g_sblk);
    bf16 *xh, *xl, *qh, *ql, *kh, *kl, *vth, *vtl, *sh, *sl, *yh, *yl;
    bf16 (*wth)[DMODEL * DMODEL], (*wtl)[DMODEL * DMODEL];
    cudaGetSymbolAddress((void**)&xh, g_xh);
    cudaGetSymbolAddress((void**)&xl, g_xl);
    cudaGetSymbolAddress((void**)&qh, g_qh);
    cudaGetSymbolAddress((void**)&ql, g_ql);
    cudaGetSymbolAddress((void**)&kh, g_kh);
    cudaGetSymbolAddress((void**)&kl, g_kl);
    cudaGetSymbolAddress((void**)&vth, g_vth);
    cudaGetSymbolAddress((void**)&vtl, g_vtl);
    cudaGetSymbolAddress((void**)&sh, g_sh);
    cudaGetSymbolAddress((void**)&sl, g_sl);
    cudaGetSymbolAddress((void**)&yh, g_yh);
    cudaGetSymbolAddress((void**)&yl, g_yl);
    cudaGetSymbolAddress((void**)&wth, g_wth);
    cudaGetSymbolAddress((void**)&wtl, g_wtl);

    cudaFuncSetAttribute(gemm_qkv,
        cudaFuncAttributeMaxDynamicSharedMemorySize, GSMEM);
    cudaFuncSetAttribute(gemm_proj_f,
        cudaFuncAttributeMaxDynamicSharedMemorySize, GSMEM);
    cudaFuncSetAttribute(gemm_scores_blk,
        cudaFuncAttributeMaxDynamicSharedMemorySize, GSMEM);
    cudaFuncSetAttribute(gemm_pv_fused,
        cudaFuncAttributeMaxDynamicSharedMemorySize, GSMEM);

    // weight transpose+split (W[K][N] -> Wt[N][K])
    const dim3 wtg(32, 32, 1);
    split_T<<<wtg, 256>>>(Wq, wth[0], wtl[0], DMODEL, DMODEL, 0, 0);
    split_T<<<wtg, 256>>>(Wk, wth[1], wtl[1], DMODEL, DMODEL, 0, 0);
    split_T<<<wtg, 256>>>(Wv, wth[2], wtl[2], DMODEL, DMODEL, 0, 0);
    split_T<<<wtg, 256>>>(Wo, wth[3], wtl[3], DMODEL, DMODEL, 0, 0);

    split_plain<<<2048, 256>>>(x, xh, xl, MTOK * DMODEL / 4);

    // merged q/k/v projections: grid (3*8, 128)
    gemm_qkv<<<dim3(24, MTOK / 128), 256, GSMEM>>>(
        xh, xl, (const bf16*)wth, (const bf16*)wtl,
        bq, bk, bv, qh, ql, kh, kl, vb);

    split_T<<<dim3(32, SEQ / 32, BATCH), 256>>>(
        vb, vth, vtl, SEQ, DMODEL,
        (size_t)SEQ * DMODEL, (size_t)SEQ * DMODEL);

    // unique score blocks (block tridiagonal)
    gemm_scores_blk<<<dim3(3, 1, BATCH * NQB), 256, GSMEM>>>(
        qh, ql, kh, kl, sblk);

    win_softmax_split<<<(NBW * WIN) / 8, 256>>>(sblk, sh, sl);

    // fused PV + window combine: writes yh/yl directly
    gemm_pv_fused<<<dim3(DMODEL / 128, MTOK / 128), 256, GSMEM>>>(
        sh, sl, vth, vtl, yh, yl);

    gemm_proj_f<<<dim3(DMODEL / 128, MTOK / 128), 256, GSMEM>>>(
        yh, yl, wth[3], wtl[3], bo, out);
}

// round 17
// speedup vs baseline: 1.2573x; 1.0165x over previous
#include <cuda_runtime.h>
#include <cuda_bf16.h>
#include <cstdint>

// ---------------- problem constants ----------------
#define BATCH 4
#define SEQ 4096
#define DMODEL 1024
#define WIN 256
#define NWIN 31              // window starts 0,128,...,3840
#define NBW (BATCH * NWIN)   // 124
#define MTOK (BATCH * SEQ)   // 16384
#define NQB 32               // 128-row query blocks per sequence

typedef __nv_bfloat16 bf16;

// ---------------- scratch (static device globals, no allocs) ----------------
// block-tridiagonal scores: [b][i][slot(d+1)] 128x128 fp32, slot d = j-i in {-1,0,1}
__device__ float g_sblk[(size_t)BATCH * NQB * 3 * 128 * 128];

__device__ bf16 g_xh[(size_t)MTOK * DMODEL];
__device__ bf16 g_xl[(size_t)MTOK * DMODEL];
__device__ bf16 g_qh[(size_t)MTOK * DMODEL];
__device__ bf16 g_ql[(size_t)MTOK * DMODEL];
__device__ bf16 g_kh[(size_t)MTOK * DMODEL];
__device__ bf16 g_kl[(size_t)MTOK * DMODEL];
__device__ bf16 g_vth[(size_t)MTOK * DMODEL];   // per-batch V^T [1024][4096]
__device__ bf16 g_vtl[(size_t)MTOK * DMODEL];
__device__ bf16 g_sh[(size_t)NBW * WIN * WIN];
__device__ bf16 g_sl[(size_t)NBW * WIN * WIN];
__device__ bf16 g_yh[(size_t)MTOK * DMODEL];
__device__ bf16 g_yl[(size_t)MTOK * DMODEL];
__device__ bf16 g_wth[4][(size_t)DMODEL * DMODEL];  // W^T splits (q,k,v,o)
__device__ bf16 g_wtl[4][(size_t)DMODEL * DMODEL];

// ---------------- primitives ----------------
__device__ __forceinline__ void mma16816(float* c, const uint32_t* a,
                                         const uint32_t* b) {
    asm volatile(
        "mma.sync.aligned.m16n8k16.row.col.f32.bf16.bf16.f32 "
        "{%0,%1,%2,%3}, {%4,%5,%6,%7}, {%8,%9}, {%0,%1,%2,%3};"
        : "+f"(c[0]), "+f"(c[1]), "+f"(c[2]), "+f"(c[3])
        : "r"(a[0]), "r"(a[1]), "r"(a[2]), "r"(a[3]), "r"(b[0]), "r"(b[1]));
}

__device__ __forceinline__ void ldsm4(uint32_t* r, uint32_t addr) {
    asm volatile(
        "ldmatrix.sync.aligned.m8n8.x4.shared.b16 {%0,%1,%2,%3}, [%4];"
        : "=r"(r[0]), "=r"(r[1]), "=r"(r[2]), "=r"(r[3])
        : "r"(addr));
}

__device__ __forceinline__ void cpa16(uint32_t s, const void* g) {
    asm volatile("cp.async.cg.shared.global [%0], [%1], 16;"
                 :: "r"(s), "l"(g) : "memory");
}
__device__ __forceinline__ void cpa_commit() {
    asm volatile("cp.async.commit_group;" ::: "memory");
}
__device__ __forceinline__ void cpa_wait0() {
    asm volatile("cp.async.wait_group 0;" ::: "memory");
}

__device__ __forceinline__ bf16 hi_of(float v) { return __float2bfloat16_rn(v); }
__device__ __forceinline__ bf16 lo_of(float v, bf16 h) {
    return __float2bfloat16_rn(v - __bfloat162float(h));
}

// ---------------- bf16x3 GEMM core (2-stage cp.async, 1 sync/tile) --------
#define SROW 40
#define MATB (128 * SROW * 2)     // bytes per matrix per stage (10240)
#define STB (4 * MATB)            // bytes per stage (40960)
#define GSMEM (2 * STB)           // 81920 bytes dynamic smem -> 2 CTAs/SM

// om=0: fp32 C.  om=1: bf16 hi/lo (Ch, Cl) row-major.
// om=2: transposed bf16 hi/lo — Ch/Cl are pre-offset to (bx-th dmodel row,
//       token base); ldc = token stride (SEQ). Used for V^T.
__device__ __forceinline__ void gemm_core(
    const bf16* __restrict__ Ah, const bf16* __restrict__ Al, int lda,
    const bf16* __restrict__ Bh, const bf16* __restrict__ Bl, int ldb,
    const float* __restrict__ bias, float scale,
    float* __restrict__ C, bf16* __restrict__ Ch, bf16* __restrict__ Cl,
    int ldc, int K, int by, int bx, int om)
{
    extern __shared__ __align__(16) char smbuf[];
    const uint32_t smu = (uint32_t)__cvta_generic_to_shared(smbuf);

    const int t = threadIdx.x;
    const int lane = t & 31;
    const int warp = t >> 5;
    const int wm = warp >> 1;
    const int wn = warp & 1;

    const int grow = t >> 2;
    const int gcg = (t & 3) * 8;
    const bf16* pAh = Ah + (size_t)(by + grow) * lda + gcg;
    const bf16* pAl = Al + (size_t)(by + grow) * lda + gcg;
    const bf16* pBh = Bh + (size_t)(bx + grow) * ldb + gcg;
    const bf16* pBl = Bl + (size_t)(bx + grow) * ldb + gcg;
    const size_t astep = (size_t)64 * lda;
    const size_t bstep = (size_t)64 * ldb;

    const uint32_t soffB = (uint32_t)(grow * SROW + gcg) * 2;
    const uint32_t r2 = 64 * SROW * 2;

    const int lg = lane & 7;
    const int sel = lane >> 3;
    const int radd = (sel & 1) * 8;
    const int cadd = (sel >> 1) * 8;
    const int radd_b = (sel >> 1) * 8;
    const int cadd_b = (sel & 1) * 8;

    float acc[2][8][4];
#pragma unroll
    for (int i = 0; i < 2; i++)
#pragma unroll
        for (int j = 0; j < 8; j++)
#pragma unroll
            for (int q = 0; q < 4; q++) acc[i][j][q] = 0.f;

#define ISSUE(kt, st)                                                     \
    {                                                                     \
        const size_t ko = (size_t)(kt) * 32;                              \
        const uint32_t d = smu + (st) * STB + soffB;                      \
        cpa16(d, pAh + ko);                                               \
        cpa16(d + r2, pAh + astep + ko);                                  \
        cpa16(d + MATB, pAl + ko);                                        \
        cpa16(d + MATB + r2, pAl + astep + ko);                           \
        cpa16(d + 2 * MATB, pBh + ko);                                    \
        cpa16(d + 2 * MATB + r2, pBh + bstep + ko);                       \
        cpa16(d + 3 * MATB, pBl + ko);                                    \
        cpa16(d + 3 * MATB + r2, pBl + bstep + ko);                       \
        cpa_commit();                                                     \
    }

    const int nt = K / 32;
    ISSUE(0, 0);

    for (int kt = 0; kt < nt; kt++) {
        const int cur = kt & 1;
        cpa_wait0();
        __syncthreads();
        // all warps done reading stage cur^1 (compute kt-1) -> safe to refill
        if (kt + 1 < nt) ISSUE(kt + 1, cur ^ 1);

        const uint32_t bAh = smu + cur * STB;
        const uint32_t bAl = bAh + MATB;
        const uint32_t bBh = bAh + 2 * MATB;
        const uint32_t bBl = bAh + 3 * MATB;

#pragma unroll
        for (int kk = 0; kk < 32; kk += 16) {
            uint32_t ah[2][4], al[2][4], bh[4][4], bl[4][4];
#pragma unroll
            for (int i = 0; i < 2; i++) {
                const uint32_t off =
                    ((wm * 32 + i * 16 + radd + lg) * SROW + kk + cadd) * 2;
                ldsm4(ah[i], bAh + off);
                ldsm4(al[i], bAl + off);
            }
#pragma unroll
            for (int jp = 0; jp < 4; jp++) {
                const uint32_t off =
                    ((wn * 64 + jp * 16 + radd_b + lg) * SROW + kk + cadd_b) * 2;
                ldsm4(bh[jp], bBh + off);
                ldsm4(bl[jp], bBl + off);
            }
#pragma unroll
            for (int i = 0; i < 2; i++)
#pragma unroll
                for (int j = 0; j < 8; j++) {
                    const uint32_t* bhp = &bh[j >> 1][(j & 1) * 2];
                    const uint32_t* blp = &bl[j >> 1][(j & 1) * 2];
                    mma16816(acc[i][j], ah[i], bhp);
                    mma16816(acc[i][j], al[i], bhp);
                    mma16816(acc[i][j], ah[i], blp);
                }
        }
    }
#undef ISSUE

    const int lrow = lane >> 2;
    const int lcol = (lane & 3) * 2;

    if (om == 2) {
        // ---- transposed V^T epilogue: stage fp32 tile, write hi/lo ----
        __syncthreads();                    // mainloop smem reads done
        float* st = (float*)smbuf;          // [128][132] = 67584 B <= GSMEM
#pragma unroll
        for (int i = 0; i < 2; i++) {
            const int rl = wm * 32 + i * 16 + lrow;
#pragma unroll
            for (int j = 0; j < 8; j++) {
                const int cl = wn * 64 + j * 8 + lcol;
                const float b0 = bias[bx + cl];
                const float b1 = bias[bx + cl + 1];
                *(float2*)&st[rl * 132 + cl] =
                    make_float2(acc[i][j][0] + b0, acc[i][j][1] + b1);
                *(float2*)&st[(rl + 8) * 132 + cl] =
                    make_float2(acc[i][j][2] + b0, acc[i][j][3] + b1);
            }
        }
        __syncthreads();
        // warp handles 16 dmodel-cols; lane = one token per group of 32
        const int cb = warp * 16;
#pragma unroll
        for (int tg = 0; tg < 4; tg++) {
            const int tok = tg * 32 + lane;
            float4 f[4];
#pragma unroll
            for (int cc = 0; cc < 4; cc++)
                f[cc] = *(const float4*)&st[tok * 132 + cb + cc * 4];
#pragma unroll
            for (int cc = 0; cc < 4; cc++) {
                const float vv[4] = {f[cc].x, f[cc].y, f[cc].z, f[cc].w};
#pragma unroll
                for (int e = 0; e < 4; e++) {
                    const int c = cb + cc * 4 + e;
                    const bf16 h = hi_of(vv[e]);
                    Ch[(size_t)c * ldc + tok] = h;
                    Cl[(size_t)c * ldc + tok] = lo_of(vv[e], h);
                }
            }
        }
        return;
    }

#pragma unroll
    for (int i = 0; i < 2; i++) {
        const int r0 = by + wm * 32 + i * 16 + lrow;
#pragma unroll
        for (int j = 0; j < 8; j++) {
            const int c = bx + wn * 64 + j * 8 + lcol;
            float b0 = 0.f, b1 = 0.f;
            if (bias) { b0 = bias[c]; b1 = bias[c + 1]; }
            const float v00 = acc[i][j][0] * scale + b0;
            const float v01 = acc[i][j][1] * scale + b1;
            const float v10 = acc[i][j][2] * scale + b0;
            const float v11 = acc[i][j][3] * scale + b1;
            if (om == 0) {
                *(float2*)&C[(size_t)r0 * ldc + c] = make_float2(v00, v01);
                *(float2*)&C[(size_t)(r0 + 8) * ldc + c] = make_float2(v10, v11);
            } else {
                const bf16 h00 = hi_of(v00), h01 = hi_of(v01);
                const bf16 h10 = hi_of(v10), h11 = hi_of(v11);
                __nv_bfloat162 hp0{h00, h01}, hp1{h10, h11};
                __nv_bfloat162 lp0{lo_of(v00, h00), lo_of(v01, h01)};
                __nv_bfloat162 lp1{lo_of(v10, h10), lo_of(v11, h11)};
                *(__nv_bfloat162*)&Ch[(size_t)r0 * ldc + c] = hp0;
                *(__nv_bfloat162*)&Ch[(size_t)(r0 + 8) * ldc + c] = hp1;
                *(__nv_bfloat162*)&Cl[(size_t)r0 * ldc + c] = lp0;
                *(__nv_bfloat162*)&Cl[(size_t)(r0 + 8) * ldc + c] = lp1;
            }
        }
    }
}

// ---------------- GEMM wrappers ----------------
// Merged Q/K/V projection: grid (24, 128). blockIdx.x>>3 selects matrix.
// V (idx==2) writes transposed hi/lo directly (no fp32 round-trip).
__global__ __launch_bounds__(256) void gemm_qkv(
    const bf16* __restrict__ xh, const bf16* __restrict__ xl,
    const bf16* __restrict__ wh, const bf16* __restrict__ wl,
    const float* __restrict__ bq, const float* __restrict__ bk,
    const float* __restrict__ bv,
    bf16* __restrict__ qh, bf16* __restrict__ ql,
    bf16* __restrict__ kh, bf16* __restrict__ kl,
    bf16* __restrict__ vth, bf16* __restrict__ vtl)
{
    const int idx = blockIdx.x >> 3;          // 0=q, 1=k, 2=v
    const int bx = (blockIdx.x & 7) * 128;
    const size_t woff = (size_t)idx * DMODEL * DMODEL;
    const int by = blockIdx.y * 128;
    if (idx == 0)
        gemm_core(xh, xl, DMODEL, wh + woff, wl + woff, DMODEL, bq, 1.f,
                  nullptr, qh, ql, DMODEL, DMODEL, by, bx, 1);
    else if (idx == 1)
        gemm_core(xh, xl, DMODEL, wh + woff, wl + woff, DMODEL, bk, 1.f,
                  nullptr, kh, kl, DMODEL, DMODEL, by, bx, 1);
    else {
        const int b = by >> 12;               // batch of this token tile
        const int pos0 = by & (SEQ - 1);
        const size_t ooff = (size_t)b * DMODEL * SEQ + (size_t)bx * SEQ + pos0;
        gemm_core(xh, xl, DMODEL, wh + woff, wl + woff, DMODEL, bv, 1.f,
                  nullptr, vth + ooff, vtl + ooff, SEQ, DMODEL, by, bx, 2);
    }
}

__global__ __launch_bounds__(256) void gemm_proj_f(
    const bf16* __restrict__ Ah, const bf16* __restrict__ Al,
    const bf16* __restrict__ Bth, const bf16* __restrict__ Btl,
    const float* __restrict__ bias, float* __restrict__ C)
{
    gemm_core(Ah, Al, DMODEL, Bth, Btl, DMODEL, bias, 1.f,
              C, nullptr, nullptr, DMODEL, DMODEL,
              blockIdx.y * 128, blockIdx.x * 128, 0);
}

// Unique score blocks: S_blk(b,i,slot) = 0.125 * Qblk(i) @ Kblk(i+slot-1)^T
__global__ __launch_bounds__(256) void gemm_scores_blk(
    const bf16* __restrict__ qh, const bf16* __restrict__ ql,
    const bf16* __restrict__ kh, const bf16* __restrict__ kl,
    float* __restrict__ sblk)
{
    const int z = blockIdx.z;          // b*NQB + i
    const int b = z >> 5;
    const int i = z & (NQB - 1);
    const int s = blockIdx.x;          // slot 0..2, j = i + s - 1
    const int j = i + s - 1;
    if (j < 0 || j >= NQB) return;
    const size_t qoff = ((size_t)b * SEQ + (size_t)i * 128) * DMODEL;
    const size_t koff = ((size_t)b * SEQ + (size_t)j * 128) * DMODEL;
    gemm_core(qh + qoff, ql + qoff, DMODEL, kh + koff, kl + koff, DMODEL,
              nullptr, 0.125f,
              sblk + ((size_t)z * 3 + s) * (128 * 128), nullptr, nullptr,
              128, DMODEL, 0, 0, 0);
}

// ---------------- fused PV + window-combine ----------------
__global__ __launch_bounds__(256) void gemm_pv_fused(
    const bf16* __restrict__ sh, const bf16* __restrict__ sl,
    const bf16* __restrict__ vth, const bf16* __restrict__ vtl,
    bf16* __restrict__ yh, bf16* __restrict__ yl)
{
    extern __shared__ __align__(16) char smbuf[];
    const uint32_t smu = (uint32_t)__cvta_generic_to_shared(smbuf);

    const int tb = blockIdx.y;
    const int b = tb >> 5;
    const int j = tb & 31;
    const int bx = blockIdx.x * 128;
    const int by = tb * 128;

    int w0, ro0, w1, ro1, nseg;
    if (j == 0)       { w0 = 0;     ro0 = 0;   w1 = 0;  ro1 = 0; nseg = 1; }
    else if (j == 31) { w0 = 30;    ro0 = 128; w1 = 30; ro1 = 128; nseg = 1; }
    else              { w0 = j - 1; ro0 = 128; w1 = j;  ro1 = 0; nseg = 2; }
    const float scale = (nseg == 2) ? 0.5f : 1.f;

    const int t = threadIdx.x;
    const int lane = t & 31;
    const int warp = t >> 5;
    const int wm = warp >> 1;
    const int wn = warp & 1;

    const int grow = t >> 2;
    const int gcg = (t & 3) * 8;

    const size_t z0 = (size_t)(b * NWIN + w0) * WIN * WIN;
    const size_t z1 = (size_t)(b * NWIN + w1) * WIN * WIN;
    const bf16* pAh0 = sh + z0 + (size_t)(ro0 + grow) * WIN + gcg;
    const bf16* pAl0 = sl + z0 + (size_t)(ro0 + grow) * WIN + gcg;
    const bf16* pAh1 = sh + z1 + (size_t)(ro1 + grow) * WIN + gcg;
    const bf16* pAl1 = sl + z1 + (size_t)(ro1 + grow) * WIN + gcg;
    const size_t vbase = (size_t)b * DMODEL * SEQ + (size_t)(bx + grow) * SEQ + gcg;
    const bf16* pBh0 = vth + vbase + 128 * w0;
    const bf16* pBl0 = vtl + vbase + 128 * w0;
    const bf16* pBh1 = vth + vbase + 128 * w1;
    const bf16* pBl1 = vtl + vbase + 128 * w1;
    const size_t astep = (size_t)64 * WIN;
    const size_t bstep = (size_t)64 * SEQ;

    const uint32_t soffB = (uint32_t)(grow * SROW + gcg) * 2;
    const uint32_t r2 = 64 * SROW * 2;

    const int lg = lane & 7;
    const int sel = lane >> 3;
    const int radd = (sel & 1) * 8;
    const int cadd = (sel >> 1) * 8;
    const int radd_b = (sel >> 1) * 8;
    const int cadd_b = (sel & 1) * 8;

    float acc[2][8][4];
#pragma unroll
    for (int i = 0; i < 2; i++)
#pragma unroll
        for (int jj = 0; jj < 8; jj++)
#pragma unroll
            for (int q = 0; q < 4; q++) acc[i][jj][q] = 0.f;

#define ISSUE_F(gt, st)                                                   \
    {                                                                     \
        const int seg = (gt) >> 3;                                        \
        const size_t ko = (size_t)((gt) & 7) * 32;                        \
        const bf16* ah_ = seg ? pAh1 : pAh0;                              \
        const bf16* al_ = seg ? pAl1 : pAl0;                              \
        const bf16* bh_ = seg ? pBh1 : pBh0;                              \
        const bf16* bl_ = seg ? pBl1 : pBl0;                              \
        const uint32_t d = smu + (st) * STB + soffB;                      \
        cpa16(d, ah_ + ko);                                               \
        cpa16(d + r2, ah_ + astep + ko);                                  \
        cpa16(d + MATB, al_ + ko);                                        \
        cpa16(d + MATB + r2, al_ + astep + ko);                           \
        cpa16(d + 2 * MATB, bh_ + ko);                                    \
        cpa16(d + 2 * MATB + r2, bh_ + bstep + ko);                       \
        cpa16(d + 3 * MATB, bl_ + ko);                                    \
        cpa16(d + 3 * MATB + r2, bl_ + bstep + ko);                       \
        cpa_commit();                                                     \
    }

    const int nt = nseg * 8;
    ISSUE_F(0, 0);

    for (int kt = 0; kt < nt; kt++) {
        const int cur = kt & 1;
        cpa_wait0();
        __syncthreads();
        if (kt + 1 < nt) ISSUE_F(kt + 1, cur ^ 1);

        const uint32_t bAh = smu + cur * STB;
        const uint32_t bAl = bAh + MATB;
        const uint32_t bBh = bAh + 2 * MATB;
        const uint32_t bBl = bAh + 3 * MATB;

#pragma unroll
        for (int kk = 0; kk < 32; kk += 16) {
            uint32_t ah[2][4], al[2][4], bh[4][4], bl[4][4];
#pragma unroll
            for (int i = 0; i < 2; i++) {
                const uint32_t off =
                    ((wm * 32 + i * 16 + radd + lg) * SROW + kk + cadd) * 2;
                ldsm4(ah[i], bAh + off);
                ldsm4(al[i], bAl + off);
            }
#pragma unroll
            for (int jp = 0; jp < 4; jp++) {
                const uint32_t off =
                    ((wn * 64 + jp * 16 + radd_b + lg) * SROW + kk + cadd_b) * 2;
                ldsm4(bh[jp], bBh + off);
                ldsm4(bl[jp], bBl + off);
            }
#pragma unroll
            for (int i = 0; i < 2; i++)
#pragma unroll
                for (int jj = 0; jj < 8; jj++) {
                    const uint32_t* bhp = &bh[jj >> 1][(jj & 1) * 2];
                    const uint32_t* blp = &bl[jj >> 1][(jj & 1) * 2];
                    mma16816(acc[i][jj], ah[i], bhp);
                    mma16816(acc[i][jj], al[i], bhp);
                    mma16816(acc[i][jj], ah[i], blp);
                }
        }
    }
#undef ISSUE_F

    const int lrow = lane >> 2;
    const int lcol = (lane & 3) * 2;
#pragma unroll
    for (int i = 0; i < 2; i++) {
        const int r0 = by + wm * 32 + i * 16 + lrow;
#pragma unroll
        for (int jj = 0; jj < 8; jj++) {
            const int c = bx + wn * 64 + jj * 8 + lcol;
            const float v00 = acc[i][jj][0] * scale;
            const float v01 = acc[i][jj][1] * scale;
            const float v10 = acc[i][jj][2] * scale;
            const float v11 = acc[i][jj][3] * scale;
            const bf16 h00 = hi_of(v00), h01 = hi_of(v01);
            const bf16 h10 = hi_of(v10), h11 = hi_of(v11);
            __nv_bfloat162 hp0{h00, h01}, hp1{h10, h11};
            __nv_bfloat162 lp0{lo_of(v00, h00), lo_of(v01, h01)};
            __nv_bfloat162 lp1{lo_of(v10, h10), lo_of(v11, h11)};
            *(__nv_bfloat162*)&yh[(size_t)r0 * DMODEL + c] = hp0;
            *(__nv_bfloat162*)&yh[(size_t)(r0 + 8) * DMODEL + c] = hp1;
            *(__nv_bfloat162*)&yl[(size_t)r0 * DMODEL + c] = lp0;
            *(__nv_bfloat162*)&yl[(size_t)(r0 + 8) * DMODEL + c] = lp1;
        }
    }
}

// ---------------- split kernels ----------------
__global__ __launch_bounds__(256) void split_plain(
    const float* __restrict__ src, bf16* __restrict__ h,
    bf16* __restrict__ l, int n4)
{
    for (int i = blockIdx.x * 256 + threadIdx.x; i < n4;
         i += gridDim.x * 256) {
        float4 v = ((const float4*)src)[i];
        bf16 hx = hi_of(v.x), hy = hi_of(v.y), hz = hi_of(v.z), hw = hi_of(v.w);
        __nv_bfloat162 h01{hx, hy}, h23{hz, hw};
        __nv_bfloat162 l01{lo_of(v.x, hx), lo_of(v.y, hy)};
        __nv_bfloat162 l23{lo_of(v.z, hz), lo_of(v.w, hw)};
        ((__nv_bfloat162*)h)[2 * i]     = h01;
        ((__nv_bfloat162*)h)[2 * i + 1] = h23;
        ((__nv_bfloat162*)l)[2 * i]     = l01;
        ((__nv_bfloat162*)l)[2 * i + 1] = l23;
    }
}

// transpose + split: src [R][Cc] fp32 -> dst [Cc][R] bf16 hi/lo (weights only)
__global__ __launch_bounds__(256) void split_T(
    const float* __restrict__ src, bf16* __restrict__ dh,
    bf16* __restrict__ dl, int R, int Cc)
{
    __shared__ float tile[32][33];
    const int c0 = blockIdx.x * 32;
    const int r0 = blockIdx.y * 32;
    const int tx = threadIdx.x & 31;
    const int ty = threadIdx.x >> 5;

#pragma unroll
    for (int k = 0; k < 4; k++)
        tile[ty + 8 * k][tx] = src[(size_t)(r0 + ty + 8 * k) * Cc + c0 + tx];
    __syncthreads();

#pragma unroll
    for (int k = 0; k < 4; k++) {
        const float v = tile[tx][ty + 8 * k];
        const bf16 hv = hi_of(v);
        const bf16 lv = lo_of(v, hv);
        const size_t o = (size_t)(c0 + ty + 8 * k) * R + r0 + tx;
        dh[o] = hv;
        dl[o] = lv;
    }
}

// ---------------- softmax + split, gathering from block-tridiagonal S -----
__global__ __launch_bounds__(256) void win_softmax_split(
    const float* __restrict__ sblk, bf16* __restrict__ sh, bf16* __restrict__ sl)
{
    const int gw = blockIdx.x * 8 + (threadIdx.x >> 5);   // 0..NBW*WIN-1
    const int lane = threadIdx.x & 31;
    const int r = gw & (WIN - 1);
    const int zw = gw >> 8;                                // b*NWIN + w
    const int b = zw / NWIN;
    const int w = zw - b * NWIN;
    const int top = (r < 128) ? 1 : 0;
    const int i = w + 1 - top;
    const int rloc = r & 127;
    const int sL = top ? 1 : 0;
    const int sR = top ? 2 : 1;

    const size_t blkbase = (size_t)(b * NQB + i) * 3 * (128 * 128)
                           + (size_t)rloc * 128;
    const float* L = sblk + blkbase + (size_t)sL * (128 * 128);
    const float* R = sblk + blkbase + (size_t)sR * (128 * 128);

    float v[8];
    float m = -1e30f;
#pragma unroll
    for (int k = 0; k < 4; k++) {
        v[k] = L[lane + 32 * k];
        v[4 + k] = R[lane + 32 * k];
    }
#pragma unroll
    for (int k = 0; k < 8; k++) m = fmaxf(m, v[k]);
#pragma unroll
    for (int o = 16; o > 0; o >>= 1)
        m = fmaxf(m, __shfl_xor_sync(0xffffffffu, m, o));

    float sum = 0.f;
#pragma unroll
    for (int k = 0; k < 8; k++) { v[k] = expf(v[k] - m); sum += v[k]; }
#pragma unroll
    for (int o = 16; o > 0; o >>= 1)
        sum += __shfl_xor_sync(0xffffffffu, sum, o);
    const float inv = 1.f / sum;

    const size_t rowb = (size_t)zw * WIN * WIN + (size_t)r * WIN;
#pragma unroll
    for (int k = 0; k < 8; k++) {
        const float p = v[k] * inv;
        const bf16 h = hi_of(p);
        const int col = (k < 4) ? (lane + 32 * k) : (128 + lane + 32 * (k - 4));
        sh[rowb + col] = h;
        sl[rowb + col] = lo_of(p, h);
    }
}

// ---------------- launch ----------------
extern "C" void kernel_launch(void* const* d_in, const int* in_sizes, int n_in,
                              void* d_out, int out_size)
{
    const float* x  = (const float*)d_in[0];
    const float* Wq = (const float*)d_in[1];
    const float* bq = (const float*)d_in[2];
    const float* Wk = (const float*)d_in[3];
    const float* bk = (const float*)d_in[4];
    const float* Wv = (const float*)d_in[5];
    const float* bv = (const float*)d_in[6];
    const float* Wo = (const float*)d_in[7];
    const float* bo = (const float*)d_in[8];
    float* out = (float*)d_out;

    float* sblk;
    cudaGetSymbolAddress((void**)&sblk, g_sblk);
    bf16 *xh, *xl, *qh, *ql, *kh, *kl, *vth, *vtl, *sh, *sl, *yh, *yl;
    bf16 (*wth)[DMODEL * DMODEL], (*wtl)[DMODEL * DMODEL];
    cudaGetSymbolAddress((void**)&xh, g_xh);
    cudaGetSymbolAddress((void**)&xl, g_xl);
    cudaGetSymbolAddress((void**)&qh, g_qh);
    cudaGetSymbolAddress((void**)&ql, g_ql);
    cudaGetSymbolAddress((void**)&kh, g_kh);
    cudaGetSymbolAddress((void**)&kl, g_kl);
    cudaGetSymbolAddress((void**)&vth, g_vth);
    cudaGetSymbolAddress((void**)&vtl, g_vtl);
    cudaGetSymbolAddress((void**)&sh, g_sh);
    cudaGetSymbolAddress((void**)&sl, g_sl);
    cudaGetSymbolAddress((void**)&yh, g_yh);
    cudaGetSymbolAddress((void**)&yl, g_yl);
    cudaGetSymbolAddress((void**)&wth, g_wth);
    cudaGetSymbolAddress((void**)&wtl, g_wtl);

    cudaFuncSetAttribute(gemm_qkv,
        cudaFuncAttributeMaxDynamicSharedMemorySize, GSMEM);
    cudaFuncSetAttribute(gemm_proj_f,
        cudaFuncAttributeMaxDynamicSharedMemorySize, GSMEM);
    cudaFuncSetAttribute(gemm_scores_blk,
        cudaFuncAttributeMaxDynamicSharedMemorySize, GSMEM);
    cudaFuncSetAttribute(gemm_pv_fused,
        cudaFuncAttributeMaxDynamicSharedMemorySize, GSMEM);

    // weight transpose+split (W[K][N] -> Wt[N][K])
    const dim3 wtg(32, 32, 1);
    split_T<<<wtg, 256>>>(Wq, wth[0], wtl[0], DMODEL, DMODEL);
    split_T<<<wtg, 256>>>(Wk, wth[1], wtl[1], DMODEL, DMODEL);
    split_T<<<wtg, 256>>>(Wv, wth[2], wtl[2], DMODEL, DMODEL);
    split_T<<<wtg, 256>>>(Wo, wth[3], wtl[3], DMODEL, DMODEL);

    split_plain<<<2048, 256>>>(x, xh, xl, MTOK * DMODEL / 4);

    // merged q/k/v projections (V writes V^T hi/lo directly)
    gemm_qkv<<<dim3(24, MTOK / 128), 256, GSMEM>>>(
        xh, xl, (const bf16*)wth, (const bf16*)wtl,
        bq, bk, bv, qh, ql, kh, kl, vth, vtl);

    // unique score blocks (block tridiagonal)
    gemm_scores_blk<<<dim3(3, 1, BATCH * NQB), 256, GSMEM>>>(
        qh, ql, kh, kl, sblk);

    win_softmax_split<<<(NBW * WIN) / 8, 256>>>(sblk, sh, sl);

    // fused PV + window combine: writes yh/yl directly
    gemm_pv_fused<<<dim3(DMODEL / 128, MTOK / 128), 256, GSMEM>>>(
        sh, sl, vth, vtl, yh, yl);

    gemm_proj_f<<<dim3(DMODEL / 128, MTOK / 128), 256, GSMEM>>>(
        yh, yl, wth[3], wtl[3], bo, out);
}